// round 13
// baseline (speedup 1.0000x reference)
#include <cuda_runtime.h>
#include <cuda_bf16.h>
#include <cuda_fp16.h>
#include <math.h>
#include <stdint.h>

// ---------------- problem constants ----------------
#define L_SEQ   4096
#define IDIM    2048
#define NHEADS  8
#define NGROUPS 2
#define HDIM    256
#define ROPED   64
#define ODIM    (NHEADS*HDIM)     // 2048
#define NKV     (NGROUPS*HDIM)    // 512
#define QKVN    (ODIM*2 + 2*NKV)  // 5120 fused projection width
#define QSCALE  0.0625f           // 256^-0.5

// ---------------- warp-MMA helpers (standard PTX, sm_80+) ----------------
__device__ __forceinline__ void ldsm_x4(uint32_t* r, uint32_t addr) {
    asm volatile("ldmatrix.sync.aligned.m8n8.x4.shared.b16 {%0,%1,%2,%3}, [%4];"
        : "=r"(r[0]), "=r"(r[1]), "=r"(r[2]), "=r"(r[3]) : "r"(addr));
}
__device__ __forceinline__ void ldsm_x4_trans(uint32_t* r, uint32_t addr) {
    asm volatile("ldmatrix.sync.aligned.m8n8.x4.trans.shared.b16 {%0,%1,%2,%3}, [%4];"
        : "=r"(r[0]), "=r"(r[1]), "=r"(r[2]), "=r"(r[3]) : "r"(addr));
}
__device__ __forceinline__ void mma16816h(float* d, const uint32_t* a, uint32_t b0, uint32_t b1) {
    asm volatile("mma.sync.aligned.m16n8k16.row.col.f32.f16.f16.f32 "
        "{%0,%1,%2,%3}, {%4,%5,%6,%7}, {%8,%9}, {%0,%1,%2,%3};"
        : "+f"(d[0]), "+f"(d[1]), "+f"(d[2]), "+f"(d[3])
        : "r"(a[0]), "r"(a[1]), "r"(a[2]), "r"(a[3]), "r"(b0), "r"(b1));
}
__device__ __forceinline__ void cp_async16(uint32_t dst, const void* src) {
    asm volatile("cp.async.cg.shared.global [%0], [%1], 16;" :: "r"(dst), "l"(src));
}
#define CP_COMMIT() asm volatile("cp.async.commit_group;" ::: "memory")
#define CP_WAIT1()  asm volatile("cp.async.wait_group 1;" ::: "memory")
#define CP_WAIT0()  asm volatile("cp.async.wait_group 0;" ::: "memory")

__device__ __forceinline__ uint32_t smem_to_u32(const void* p) {
    uint32_t a;
    asm("{ .reg .u64 t; cvta.to.shared.u64 t, %1; cvt.u32.u64 %0, t; }" : "=r"(a) : "l"(p));
    return a;
}
__device__ __forceinline__ uint32_t pack_h2(__half a, __half b) {
    __half2 t = __halves2half2(a, b);
    return *reinterpret_cast<uint32_t*>(&t);
}

// ---------------- scratch (device globals) ----------------
__device__ float  g_qkvraw[(size_t)L_SEQ * QKVN];   // [q|gate interleaved per head (4096)] [k (512)] [v (512)]
__device__ __half g_gate16[(size_t)L_SEQ * ODIM];

// fp16 operands
__device__ __half g_x16   [(size_t)L_SEQ * IDIM];
__device__ __half g_wqkv16[(size_t)QKVN * IDIM];    // rows 0-4095 wq^T, 4096-4607 wk^T, 4608-5119 wv^T
__device__ __half g_wo16  [(size_t)IDIM * ODIM];
__device__ __half g_y     [(size_t)L_SEQ * ODIM];
// attention operands (single fp16)
__device__ __half g_q16 [(size_t)L_SEQ * ODIM];     // pre-scaled
__device__ __half g_k16 [(size_t)L_SEQ * NKV];
__device__ __half g_v16 [(size_t)L_SEQ * NKV];

// ---------------- cast kernel: fp32 -> fp16 ----------------
__global__ __launch_bounds__(256) void cast_h_kernel(
    const float* __restrict__ in, __half* __restrict__ out, size_t n4)
{
    size_t i = (size_t)blockIdx.x * blockDim.x + threadIdx.x;
    size_t stride = (size_t)gridDim.x * blockDim.x;
    for (; i < n4; i += stride) {
        float4 v = reinterpret_cast<const float4*>(in)[i];
        __half2 a = __halves2half2(__float2half_rn(v.x), __float2half_rn(v.y));
        __half2 b = __halves2half2(__float2half_rn(v.z), __float2half_rn(v.w));
        reinterpret_cast<__half2*>(out)[i*2]   = a;
        reinterpret_cast<__half2*>(out)[i*2+1] = b;
    }
}

// ---------------- transpose: W[K][N] fp32 -> Wt [N][K] fp16 ----------------
__global__ __launch_bounds__(256) void transpose_h_kernel(
    const float* __restrict__ W, __half* __restrict__ T, int Kdim, int Ndim)
{
    __shared__ float tile[32][33];
    int n0 = blockIdx.x * 32;
    int k0 = blockIdx.y * 32;
    int tx = threadIdx.x & 31;
    int ty = threadIdx.x >> 5;
#pragma unroll
    for (int r = 0; r < 4; r++)
        tile[ty + 8*r][tx] = W[(size_t)(k0 + ty + 8*r) * Ndim + n0 + tx];
    __syncthreads();
#pragma unroll
    for (int r = 0; r < 4; r++) {
        float v = tile[tx][ty + 8*r];
        T[(size_t)(n0 + ty + 8*r) * Kdim + k0 + tx] = __float2half_rn(v);
    }
}

// ---------------- 1-term fp16 GEMM: C = A(fp16) @ B(fp16)^T ----------------
#define GBK 32
#define NCHUNK (IDIM / GBK)            // 64
#define RS 80                          // smem row stride bytes
#define MAT_BYTES (128 * RS)           // 10240
#define MAT2_STAGE (2 * MAT_BYTES)     // 20480
#define GEMM1_SMEM (2 * MAT2_STAGE)    // 40960

__global__ __launch_bounds__(256) void mma_gemmh(
    const __half* __restrict__ A, const __half* __restrict__ B,
    float* __restrict__ C, int N)
{
    extern __shared__ char smem[];
    const uint32_t sb = smem_to_u32(smem);

    const int tid  = threadIdx.x;
    const int lane = tid & 31;
    const int wid  = tid >> 5;
    const int wm   = wid & 1;
    const int wn   = wid >> 1;
    const int m0   = blockIdx.y * 128;
    const int n0   = blockIdx.x * 128;

    auto issue_loads = [&](int chunk) {
        const int stage = chunk & 1;
        const uint32_t s0 = sb + stage * MAT2_STAGE;
#pragma unroll
        for (int j = 0; j < 4; j++) {
            int idx = tid + 256 * j;          // 0..1023
            int mat = idx >> 9;               // 0=A,1=B
            int wi  = idx & 511;
            int row = wi >> 2;
            int c   = wi & 3;
            const __half* gp = (mat == 0) ? A + (size_t)(m0 + row) * IDIM
                                          : B + (size_t)(n0 + row) * IDIM;
            cp_async16(s0 + mat * MAT_BYTES + row * RS + c * 16,
                       gp + chunk * GBK + c * 8);
        }
    };

    float acc[4][4][4];
#pragma unroll
    for (int mi = 0; mi < 4; mi++)
#pragma unroll
        for (int ni = 0; ni < 4; ni++)
#pragma unroll
            for (int r = 0; r < 4; r++) acc[mi][ni][r] = 0.0f;

    const uint32_t a_row = wm * 64 + (lane & 15);
    const uint32_t b_row = wn * 32 + (lane & 15);
    const uint32_t colb  = (lane >> 4) * 16;

    issue_loads(0); CP_COMMIT();

    for (int i = 0; i < NCHUNK; i++) {
        const int stage = i & 1;
        if (i + 1 < NCHUNK) { issue_loads(i + 1); CP_COMMIT(); CP_WAIT1(); }
        else                { CP_WAIT0(); }
        __syncthreads();

        const uint32_t sA = sb + stage * MAT2_STAGE;
        const uint32_t sB = sA + MAT_BYTES;

#pragma unroll
        for (int ks = 0; ks < 2; ks++) {
            const uint32_t kb = ks * 32 + colb;
            uint32_t a[4][4], b[2][4];
#pragma unroll
            for (int mi = 0; mi < 4; mi++)
                ldsm_x4(a[mi], sA + (a_row + mi * 16) * RS + kb);
#pragma unroll
            for (int nt = 0; nt < 2; nt++)
                ldsm_x4(b[nt], sB + (b_row + nt * 16) * RS + kb);
#pragma unroll
            for (int mi = 0; mi < 4; mi++) {
#pragma unroll
                for (int ni = 0; ni < 4; ni++) {
                    const int nt = ni >> 1, sub = ni & 1;
                    mma16816h(acc[mi][ni], a[mi], b[nt][sub], b[nt][2 + sub]);
                }
            }
        }
        __syncthreads();
    }

    const int er = lane >> 2;
    const int ec = (lane & 3) * 2;
#pragma unroll
    for (int mi = 0; mi < 4; mi++) {
#pragma unroll
        for (int ni = 0; ni < 4; ni++) {
            int row = m0 + wm * 64 + mi * 16 + er;
            int col = n0 + wn * 32 + ni * 8 + ec;
            *reinterpret_cast<float2*>(&C[(size_t)row * N + col]) =
                make_float2(acc[mi][ni][0], acc[mi][ni][1]);
            *reinterpret_cast<float2*>(&C[(size_t)(row + 8) * N + col]) =
                make_float2(acc[mi][ni][2], acc[mi][ni][3]);
        }
    }
}

// ---------------- warp-per-row RMSNorm + RoPE for Q (+ gate fp16) ----------------
// 8 warps/block, each warp one (l,h) row: 8 elems/lane, shuffle-only reduction.
__global__ __launch_bounds__(256) void qnorm_rope_kernel(
    const float* __restrict__ cosb, const float* __restrict__ sinb,
    const float* __restrict__ gamma)
{
    const int ridx = blockIdx.x * 8 + (threadIdx.x >> 5);  // 0..32767
    const int lane = threadIdx.x & 31;
    const int l = ridx >> 3, h = ridx & 7;
    const float* row = g_qkvraw + (size_t)l * QKVN + h * 512;

    float4 a = *reinterpret_cast<const float4*>(row + lane * 8);
    float4 b = *reinterpret_cast<const float4*>(row + lane * 8 + 4);
    float y[8] = {a.x, a.y, a.z, a.w, b.x, b.y, b.z, b.w};

    float s = 0.0f;
#pragma unroll
    for (int j = 0; j < 8; j++) s += y[j] * y[j];
#pragma unroll
    for (int o = 16; o > 0; o >>= 1) s += __shfl_xor_sync(0xffffffffu, s, o);
    float rstd = rsqrtf(s * (1.0f / 256.0f) + 1e-6f);

    float4 ga = *reinterpret_cast<const float4*>(gamma + lane * 8);
    float4 gb = *reinterpret_cast<const float4*>(gamma + lane * 8 + 4);
    float gm[8] = {ga.x, ga.y, ga.z, ga.w, gb.x, gb.y, gb.z, gb.w};
#pragma unroll
    for (int j = 0; j < 8; j++) y[j] *= rstd * gm[j];

    // RoPE on d<64 (lanes 0..7); partner d±32 = shfl_xor lane 4
    float oth[8];
#pragma unroll
    for (int j = 0; j < 8; j++) oth[j] = __shfl_xor_sync(0xffffffffu, y[j], 4);
    if (lane < 8) {
        const float* cb = cosb + (size_t)l * ROPED + lane * 8;
        const float* sbp = sinb + (size_t)l * ROPED + lane * 8;
#pragma unroll
        for (int j = 0; j < 8; j++) {
            float rot = (lane < 4) ? -oth[j] : oth[j];
            y[j] = y[j] * cb[j] + rot * sbp[j];
        }
    }

    // gate
    float4 g0 = *reinterpret_cast<const float4*>(row + 256 + lane * 8);
    float4 g1 = *reinterpret_cast<const float4*>(row + 256 + lane * 8 + 4);
    float gv[8] = {g0.x, g0.y, g0.z, g0.w, g1.x, g1.y, g1.z, g1.w};

    size_t o = (size_t)l * ODIM + h * HDIM + lane * 8;
    uint32_t qw[4], gw[4];
#pragma unroll
    for (int j = 0; j < 4; j++) {
        qw[j] = pack_h2(__float2half_rn(y[j*2] * QSCALE), __float2half_rn(y[j*2+1] * QSCALE));
        gw[j] = pack_h2(__float2half_rn(gv[j*2]), __float2half_rn(gv[j*2+1]));
    }
    *reinterpret_cast<uint4*>(&g_q16[o])    = make_uint4(qw[0], qw[1], qw[2], qw[3]);
    *reinterpret_cast<uint4*>(&g_gate16[o]) = make_uint4(gw[0], gw[1], gw[2], gw[3]);
}

// ---------------- warp-per-row RMSNorm + RoPE for K + V cast ----------------
__global__ __launch_bounds__(256) void knorm_rope_v_kernel(
    const float* __restrict__ cosb, const float* __restrict__ sinb,
    const float* __restrict__ gamma)
{
    const int ridx = blockIdx.x * 8 + (threadIdx.x >> 5);  // 0..8191
    const int lane = threadIdx.x & 31;
    const int l = ridx >> 1, g = ridx & 1;
    const float* krow = g_qkvraw + (size_t)l * QKVN + 4096 + g * HDIM;
    const float* vrow = g_qkvraw + (size_t)l * QKVN + 4608 + g * HDIM;

    float4 a = *reinterpret_cast<const float4*>(krow + lane * 8);
    float4 b = *reinterpret_cast<const float4*>(krow + lane * 8 + 4);
    float y[8] = {a.x, a.y, a.z, a.w, b.x, b.y, b.z, b.w};

    float s = 0.0f;
#pragma unroll
    for (int j = 0; j < 8; j++) s += y[j] * y[j];
#pragma unroll
    for (int o = 16; o > 0; o >>= 1) s += __shfl_xor_sync(0xffffffffu, s, o);
    float rstd = rsqrtf(s * (1.0f / 256.0f) + 1e-6f);

    float4 ga = *reinterpret_cast<const float4*>(gamma + lane * 8);
    float4 gb = *reinterpret_cast<const float4*>(gamma + lane * 8 + 4);
    float gm[8] = {ga.x, ga.y, ga.z, ga.w, gb.x, gb.y, gb.z, gb.w};
#pragma unroll
    for (int j = 0; j < 8; j++) y[j] *= rstd * gm[j];

    float oth[8];
#pragma unroll
    for (int j = 0; j < 8; j++) oth[j] = __shfl_xor_sync(0xffffffffu, y[j], 4);
    if (lane < 8) {
        const float* cb = cosb + (size_t)l * ROPED + lane * 8;
        const float* sbp = sinb + (size_t)l * ROPED + lane * 8;
#pragma unroll
        for (int j = 0; j < 8; j++) {
            float rot = (lane < 4) ? -oth[j] : oth[j];
            y[j] = y[j] * cb[j] + rot * sbp[j];
        }
    }

    float4 v0 = *reinterpret_cast<const float4*>(vrow + lane * 8);
    float4 v1 = *reinterpret_cast<const float4*>(vrow + lane * 8 + 4);
    float vv[8] = {v0.x, v0.y, v0.z, v0.w, v1.x, v1.y, v1.z, v1.w};

    size_t o = (size_t)l * NKV + g * HDIM + lane * 8;
    uint32_t kw[4], vw[4];
#pragma unroll
    for (int j = 0; j < 4; j++) {
        kw[j] = pack_h2(__float2half_rn(y[j*2]), __float2half_rn(y[j*2+1]));
        vw[j] = pack_h2(__float2half_rn(vv[j*2]), __float2half_rn(vv[j*2+1]));
    }
    *reinterpret_cast<uint4*>(&g_k16[o]) = make_uint4(kw[0], kw[1], kw[2], kw[3]);
    *reinterpret_cast<uint4*>(&g_v16[o]) = make_uint4(vw[0], vw[1], vw[2], vw[3]);
}

// ---------------- MMA flash attention (single fp16), BR=BC=64, D=256 ----------------
#define AQ   0
#define AK   32768
#define AV   65536
#define AP   98304                  // 64 x 128B (fp16 P, swizzled)
#define APM  (AP + 8192)            // partial max: 2 x 64 floats
#define APS  (APM + 512)            // partial sum: 2 x 64 floats
#define AMR  (APS + 512)
#define ALR  (AMR + 256)
#define ACR  (ALR + 256)
#define ATT_SMEM (ACR + 256)        // 108288

__device__ __forceinline__ uint32_t sw512(int row, int g) {
    return (uint32_t)(row * 512 + ((g ^ (row & 7)) << 4));
}
__device__ __forceinline__ uint32_t sw128(int row, int g) {
    return (uint32_t)(row * 128 + ((g ^ (row & 7)) << 4));
}

__global__ __launch_bounds__(256, 2) void attn_mma_kernel()
{
    extern __shared__ char sm[];
    const uint32_t sb = smem_to_u32(sm);
    const int tid  = threadIdx.x;
    const int lane = tid & 31;
    const int wid  = tid >> 5;
    const int qt   = gridDim.x - 1 - blockIdx.x;   // big tiles first
    const int h    = blockIdx.y;
    const int g    = h >> 2;
    const int i0   = qt * 64;

    float* pmax = reinterpret_cast<float*>(sm + APM);
    float* psum = reinterpret_cast<float*>(sm + APS);
    float* mrow = reinterpret_cast<float*>(sm + AMR);
    float* lrow = reinterpret_cast<float*>(sm + ALR);
    float* crow = reinterpret_cast<float*>(sm + ACR);

    auto load_k = [&](int j0) {
        const size_t rbase = ((size_t)j0 * NGROUPS + g) * HDIM;
        const size_t rstr  = (size_t)NGROUPS * HDIM;
#pragma unroll
        for (int i = 0; i < 8; i++) {
            int idx = tid + 256 * i;
            int row = idx >> 5, gr = idx & 31;
            cp_async16(sb + AK + sw512(row, gr),
                       (const char*)g_k16 + (rbase + (size_t)row * rstr) * 2 + gr * 16);
        }
    };
    auto load_v = [&](int j0) {
        const size_t rbase = ((size_t)j0 * NGROUPS + g) * HDIM;
        const size_t rstr  = (size_t)NGROUPS * HDIM;
#pragma unroll
        for (int i = 0; i < 8; i++) {
            int idx = tid + 256 * i;
            int row = idx >> 5, gr = idx & 31;
            cp_async16(sb + AV + sw512(row, gr),
                       (const char*)g_v16 + (rbase + (size_t)row * rstr) * 2 + gr * 16);
        }
    };

    // ---- prolog: Q, K(0), V(0) ----
    {
        const char* q16 = (const char*)(g_q16 + ((size_t)i0 * NHEADS + h) * HDIM);
        const size_t rstr = (size_t)NHEADS * HDIM * 2;
#pragma unroll
        for (int i = 0; i < 8; i++) {
            int idx = tid + 256 * i;
            int row = idx >> 5, gr = idx & 31;
            cp_async16(sb + AQ + sw512(row, gr), q16 + (size_t)row * rstr + gr * 16);
        }
    }
    CP_COMMIT();
    load_k(0); CP_COMMIT();
    if (tid < 64) { mrow[tid] = -INFINITY; lrow[tid] = 0.0f; }
    load_v(0); CP_COMMIT();

    const int wm = wid & 3;
    const int wn = wid >> 2;
    const int er = lane >> 2;
    const int ec = (lane & 3) * 2;
    const int kgl = lane >> 4;

    float oacc[16][4];
#pragma unroll
    for (int t = 0; t < 16; t++)
#pragma unroll
        for (int r = 0; r < 4; r++) oacc[t][r] = 0.0f;

    for (int j0 = 0; j0 <= i0; j0 += 64) {
        CP_WAIT1();                // Q (+K) ready
        __syncthreads();

        // ---- S = Q K^T ----
        float sacc[4][4];
#pragma unroll
        for (int t = 0; t < 4; t++)
#pragma unroll
            for (int r = 0; r < 4; r++) sacc[t][r] = 0.0f;

        const int arow  = wm * 16 + (lane & 15);
        const int brow0 = wn * 32 + (lane & 15);
#pragma unroll 4
        for (int ks = 0; ks < 16; ks++) {
            int kg = ks * 2 + kgl;
            uint32_t a[4], b[2][4];
            ldsm_x4(a, sb + AQ + sw512(arow, kg));
            ldsm_x4(b[0], sb + AK + sw512(brow0, kg));
            ldsm_x4(b[1], sb + AK + sw512(brow0 + 16, kg));
#pragma unroll
            for (int nt = 0; nt < 2; nt++)
#pragma unroll
                for (int sub = 0; sub < 2; sub++)
                    mma16816h(sacc[nt * 2 + sub], a, b[nt][sub], b[nt][2 + sub]);
        }

        // ---- fused softmax (register-resident) ----
        const int r0 = wm * 16 + er;
        const int r1 = r0 + 8;
        {
            const int lim0 = i0 + r0 - j0;
            const int lim1 = lim0 + 8;
            float m0 = -INFINITY, m1 = -INFINITY;
#pragma unroll
            for (int t = 0; t < 4; t++) {
                int col = wn * 32 + (t >> 1) * 16 + (t & 1) * 8 + ec;
                if (col > lim0)     sacc[t][0] = -INFINITY;
                if (col + 1 > lim0) sacc[t][1] = -INFINITY;
                if (col > lim1)     sacc[t][2] = -INFINITY;
                if (col + 1 > lim1) sacc[t][3] = -INFINITY;
                m0 = fmaxf(m0, fmaxf(sacc[t][0], sacc[t][1]));
                m1 = fmaxf(m1, fmaxf(sacc[t][2], sacc[t][3]));
            }
            m0 = fmaxf(m0, __shfl_xor_sync(0xffffffffu, m0, 1));
            m0 = fmaxf(m0, __shfl_xor_sync(0xffffffffu, m0, 2));
            m1 = fmaxf(m1, __shfl_xor_sync(0xffffffffu, m1, 1));
            m1 = fmaxf(m1, __shfl_xor_sync(0xffffffffu, m1, 2));
            if ((lane & 3) == 0) { pmax[wn * 64 + r0] = m0; pmax[wn * 64 + r1] = m1; }
            __syncthreads();

            float mn0 = fmaxf(fmaxf(pmax[r0], pmax[64 + r0]), mrow[r0]);
            float mn1 = fmaxf(fmaxf(pmax[r1], pmax[64 + r1]), mrow[r1]);
            float s0 = 0.0f, s1 = 0.0f;
            uint32_t pw0[4], pw1[4];
#pragma unroll
            for (int t = 0; t < 4; t++) {
                float p00 = __expf(sacc[t][0] - mn0);
                float p01 = __expf(sacc[t][1] - mn0);
                float p10 = __expf(sacc[t][2] - mn1);
                float p11 = __expf(sacc[t][3] - mn1);
                s0 += p00 + p01; s1 += p10 + p11;
                pw0[t] = pack_h2(__float2half_rn(p00), __float2half_rn(p01));
                pw1[t] = pack_h2(__float2half_rn(p10), __float2half_rn(p11));
            }
            s0 += __shfl_xor_sync(0xffffffffu, s0, 1);
            s0 += __shfl_xor_sync(0xffffffffu, s0, 2);
            s1 += __shfl_xor_sync(0xffffffffu, s1, 1);
            s1 += __shfl_xor_sync(0xffffffffu, s1, 2);
#pragma unroll
            for (int t = 0; t < 4; t++) {
                int gidx = wn * 4 + (t >> 1) * 2 + (t & 1);
                *reinterpret_cast<uint32_t*>(sm + AP + sw128(r0, gidx) + (lane & 3) * 4) = pw0[t];
                *reinterpret_cast<uint32_t*>(sm + AP + sw128(r1, gidx) + (lane & 3) * 4) = pw1[t];
            }
            if ((lane & 3) == 0) { psum[wn * 64 + r0] = s0; psum[wn * 64 + r1] = s1; }
            __syncthreads();

            if (tid < 64) {
                float mold = mrow[tid];
                float mnew = fmaxf(fmaxf(pmax[tid], pmax[64 + tid]), mold);
                float corr = __expf(mold - mnew);
                lrow[tid] = lrow[tid] * corr + psum[tid] + psum[64 + tid];
                mrow[tid] = mnew;
                crow[tid] = corr;
            }
        }

        if (j0 + 64 <= i0) load_k(j0 + 64);
        CP_COMMIT();
        CP_WAIT1();               // V(j0) ready
        __syncthreads();          // also publishes crow/lrow updates

        // ---- rescale O, then O += P V ----
        {
            float c0 = crow[r0];
            float c1 = crow[r1];
#pragma unroll
            for (int t = 0; t < 16; t++) {
                oacc[t][0] *= c0; oacc[t][1] *= c0;
                oacc[t][2] *= c1; oacc[t][3] *= c1;
            }
        }
        const int prow = wm * 16 + (lane & 15);
        const int vk   = lane & 15;
        const int vng  = lane >> 4;
#pragma unroll
        for (int ks = 0; ks < 4; ks++) {
            uint32_t a[4];
            ldsm_x4(a, sb + AP + sw128(prow, ks * 2 + kgl));
            int krow = ks * 16 + vk;
#pragma unroll
            for (int ng = 0; ng < 8; ng++) {
                uint32_t vv[4];
                int gv = wn * 16 + ng * 2 + vng;
                ldsm_x4_trans(vv, sb + AV + sw512(krow, gv));
#pragma unroll
                for (int sub = 0; sub < 2; sub++)
                    mma16816h(oacc[ng * 2 + sub], a, vv[2 * sub], vv[2 * sub + 1]);
            }
        }
        __syncthreads();          // V buffer dead

        if (j0 + 64 <= i0) load_v(j0 + 64);
        CP_COMMIT();
    }

    // ---- epilogue: 1/l, sigmoid gate (fp16), write single fp16 y ----
    {
        const int r0 = wm * 16 + er;
        const float li0 = 1.0f / lrow[r0];
        const float li1 = 1.0f / lrow[r0 + 8];
        const size_t base0 = (size_t)(i0 + r0) * ODIM + h * HDIM;
        const size_t base1 = (size_t)(i0 + r0 + 8) * ODIM + h * HDIM;
#pragma unroll
        for (int t = 0; t < 16; t++) {
            int col = wn * 128 + (t >> 1) * 16 + (t & 1) * 8 + ec;
            __half2 gh0 = *reinterpret_cast<const __half2*>(&g_gate16[base0 + col]);
            __half2 gh1 = *reinterpret_cast<const __half2*>(&g_gate16[base1 + col]);
            float2 gt0 = __half22float2(gh0);
            float2 gt1 = __half22float2(gh1);
            float v00 = oacc[t][0] * li0 * (1.0f / (1.0f + __expf(-gt0.x)));
            float v01 = oacc[t][1] * li0 * (1.0f / (1.0f + __expf(-gt0.y)));
            float v10 = oacc[t][2] * li1 * (1.0f / (1.0f + __expf(-gt1.x)));
            float v11 = oacc[t][3] * li1 * (1.0f / (1.0f + __expf(-gt1.y)));
            *reinterpret_cast<__half2*>(&g_y[base0 + col]) =
                __halves2half2(__float2half_rn(v00), __float2half_rn(v01));
            *reinterpret_cast<__half2*>(&g_y[base1 + col]) =
                __halves2half2(__float2half_rn(v10), __float2half_rn(v11));
        }
    }
}

// ---------------- launch ----------------
extern "C" void kernel_launch(void* const* d_in, const int* in_sizes, int n_in,
                              void* d_out, int out_size)
{
    const float* x    = (const float*)d_in[0];
    const float* cosb = (const float*)d_in[1];
    const float* sinb = (const float*)d_in[2];
    const float* wq   = (const float*)d_in[4];
    const float* wk   = (const float*)d_in[5];
    const float* wv   = (const float*)d_in[6];
    const float* wo   = (const float*)d_in[7];
    const float* qg   = (const float*)d_in[8];
    const float* kg   = (const float*)d_in[9];
    float* out        = (float*)d_out;

    float* p_qkvraw;
    cudaGetSymbolAddress((void**)&p_qkvraw, g_qkvraw);

    __half *p_x16, *p_wqkv16, *p_wo16, *p_y;
    cudaGetSymbolAddress((void**)&p_x16,    g_x16);
    cudaGetSymbolAddress((void**)&p_wqkv16, g_wqkv16);
    cudaGetSymbolAddress((void**)&p_wo16,   g_wo16);
    cudaGetSymbolAddress((void**)&p_y,      g_y);

    cudaFuncSetAttribute(mma_gemmh, cudaFuncAttributeMaxDynamicSharedMemorySize, GEMM1_SMEM);
    cudaFuncSetAttribute(attn_mma_kernel, cudaFuncAttributeMaxDynamicSharedMemorySize, ATT_SMEM);

    // 0) operand prep (all fp16, 1-term); wq/wk/wv transpose into one fused buffer
    cast_h_kernel<<<2048, 256>>>(x, p_x16, (size_t)L_SEQ * IDIM / 4);
    transpose_h_kernel<<<dim3((ODIM*2)/32, IDIM/32), 256>>>(wq, p_wqkv16, IDIM, ODIM*2);
    transpose_h_kernel<<<dim3(NKV/32, IDIM/32), 256>>>(
        wk, p_wqkv16 + (size_t)4096 * IDIM, IDIM, NKV);
    transpose_h_kernel<<<dim3(NKV/32, IDIM/32), 256>>>(
        wv, p_wqkv16 + (size_t)4608 * IDIM, IDIM, NKV);
    transpose_h_kernel<<<dim3(IDIM/32, ODIM/32), 256>>>(wo, p_wo16, ODIM, IDIM);

    // 1) fused QKV projection: N = 5120
    mma_gemmh<<<dim3(QKVN/128, L_SEQ/128), 256, GEMM1_SMEM>>>(p_x16, p_wqkv16, p_qkvraw, QKVN);

    // 2) warp-per-row norms + RoPE -> single fp16
    qnorm_rope_kernel<<<L_SEQ * NHEADS / 8,  256>>>(cosb, sinb, qg);
    knorm_rope_v_kernel<<<L_SEQ * NGROUPS / 8, 256>>>(cosb, sinb, kg);

    // 3) MMA flash attention (fused register softmax, 2 CTAs/SM) -> fp16 y
    attn_mma_kernel<<<dim3(L_SEQ / 64, NHEADS), 256, ATT_SMEM>>>();

    // 4) output projection: 1-term fp16
    mma_gemmh<<<dim3(IDIM/128, L_SEQ/128), 256, GEMM1_SMEM>>>(p_y, p_wo16, out, IDIM);
}

// round 14
// speedup vs baseline: 1.5237x; 1.5237x over previous
#include <cuda_runtime.h>
#include <cuda_bf16.h>
#include <cuda_fp16.h>
#include <math.h>
#include <stdint.h>

// ---------------- problem constants ----------------
#define L_SEQ   4096
#define IDIM    2048
#define NHEADS  8
#define NGROUPS 2
#define HDIM    256
#define ROPED   64
#define ODIM    (NHEADS*HDIM)     // 2048
#define NKV     (NGROUPS*HDIM)    // 512
#define QSCALE  0.0625f           // 256^-0.5

// ---------------- warp-MMA helpers (standard PTX, sm_80+) ----------------
__device__ __forceinline__ void ldsm_x4(uint32_t* r, uint32_t addr) {
    asm volatile("ldmatrix.sync.aligned.m8n8.x4.shared.b16 {%0,%1,%2,%3}, [%4];"
        : "=r"(r[0]), "=r"(r[1]), "=r"(r[2]), "=r"(r[3]) : "r"(addr));
}
__device__ __forceinline__ void ldsm_x4_trans(uint32_t* r, uint32_t addr) {
    asm volatile("ldmatrix.sync.aligned.m8n8.x4.trans.shared.b16 {%0,%1,%2,%3}, [%4];"
        : "=r"(r[0]), "=r"(r[1]), "=r"(r[2]), "=r"(r[3]) : "r"(addr));
}
__device__ __forceinline__ void mma16816h(float* d, const uint32_t* a, uint32_t b0, uint32_t b1) {
    asm volatile("mma.sync.aligned.m16n8k16.row.col.f32.f16.f16.f32 "
        "{%0,%1,%2,%3}, {%4,%5,%6,%7}, {%8,%9}, {%0,%1,%2,%3};"
        : "+f"(d[0]), "+f"(d[1]), "+f"(d[2]), "+f"(d[3])
        : "r"(a[0]), "r"(a[1]), "r"(a[2]), "r"(a[3]), "r"(b0), "r"(b1));
}
__device__ __forceinline__ void cp_async16(uint32_t dst, const void* src) {
    asm volatile("cp.async.cg.shared.global [%0], [%1], 16;" :: "r"(dst), "l"(src));
}
#define CP_COMMIT() asm volatile("cp.async.commit_group;" ::: "memory")
#define CP_WAIT1()  asm volatile("cp.async.wait_group 1;" ::: "memory")
#define CP_WAIT0()  asm volatile("cp.async.wait_group 0;" ::: "memory")

__device__ __forceinline__ uint32_t smem_to_u32(const void* p) {
    uint32_t a;
    asm("{ .reg .u64 t; cvta.to.shared.u64 t, %1; cvt.u32.u64 %0, t; }" : "=r"(a) : "l"(p));
    return a;
}
__device__ __forceinline__ uint32_t pack_h2(__half a, __half b) {
    __half2 t = __halves2half2(a, b);
    return *reinterpret_cast<uint32_t*>(&t);
}

// ---------------- scratch (device globals) ----------------
__device__ float  g_qraw [(size_t)L_SEQ * (ODIM*2)];
__device__ __half g_gate16[(size_t)L_SEQ * ODIM];
__device__ float  g_kvraw[(size_t)L_SEQ * 1024];    // cols 0-511 = K, 512-1023 = V

// fp16 operands (all GEMMs 1-term fp16)
__device__ __half g_x16  [(size_t)L_SEQ * IDIM];
__device__ __half g_wq16 [(size_t)(ODIM*2) * IDIM];
__device__ __half g_wkv16[(size_t)1024 * IDIM];     // rows 0-511 wk^T, 512-1023 wv^T
__device__ __half g_wo16 [(size_t)IDIM * ODIM];
__device__ __half g_y    [(size_t)L_SEQ * ODIM];
// attention operands (single fp16)
__device__ __half g_q16 [(size_t)L_SEQ * ODIM];     // pre-scaled
__device__ __half g_k16 [(size_t)L_SEQ * NKV];
__device__ __half g_v16 [(size_t)L_SEQ * NKV];

// ---------------- cast kernel: fp32 -> fp16 ----------------
__global__ __launch_bounds__(256) void cast_h_kernel(
    const float* __restrict__ in, __half* __restrict__ out, size_t n4)
{
    size_t i = (size_t)blockIdx.x * blockDim.x + threadIdx.x;
    size_t stride = (size_t)gridDim.x * blockDim.x;
    for (; i < n4; i += stride) {
        float4 v = reinterpret_cast<const float4*>(in)[i];
        __half2 a = __halves2half2(__float2half_rn(v.x), __float2half_rn(v.y));
        __half2 b = __halves2half2(__float2half_rn(v.z), __float2half_rn(v.w));
        reinterpret_cast<__half2*>(out)[i*2]   = a;
        reinterpret_cast<__half2*>(out)[i*2+1] = b;
    }
}

// ---------------- transpose: W[K][N] fp32 -> Wt [N][K] fp16 ----------------
__global__ __launch_bounds__(256) void transpose_h_kernel(
    const float* __restrict__ W, __half* __restrict__ T, int Kdim, int Ndim)
{
    __shared__ float tile[32][33];
    int n0 = blockIdx.x * 32;
    int k0 = blockIdx.y * 32;
    int tx = threadIdx.x & 31;
    int ty = threadIdx.x >> 5;
#pragma unroll
    for (int r = 0; r < 4; r++)
        tile[ty + 8*r][tx] = W[(size_t)(k0 + ty + 8*r) * Ndim + n0 + tx];
    __syncthreads();
#pragma unroll
    for (int r = 0; r < 4; r++) {
        float v = tile[tx][ty + 8*r];
        T[(size_t)(n0 + ty + 8*r) * Kdim + k0 + tx] = __float2half_rn(v);
    }
}

// ---------------- 1-term fp16 GEMM: C = A(fp16) @ B(fp16)^T ----------------
#define GBK 32
#define NCHUNK (IDIM / GBK)            // 64
#define RS 80                          // smem row stride bytes
#define MAT_BYTES (128 * RS)           // 10240
#define MAT2_STAGE (2 * MAT_BYTES)     // 20480
#define GEMM1_SMEM (2 * MAT2_STAGE)    // 40960

__global__ __launch_bounds__(256) void mma_gemmh(
    const __half* __restrict__ A, const __half* __restrict__ B,
    float* __restrict__ C, int N)
{
    extern __shared__ char smem[];
    const uint32_t sb = smem_to_u32(smem);

    const int tid  = threadIdx.x;
    const int lane = tid & 31;
    const int wid  = tid >> 5;
    const int wm   = wid & 1;
    const int wn   = wid >> 1;
    const int m0   = blockIdx.y * 128;
    const int n0   = blockIdx.x * 128;

    auto issue_loads = [&](int chunk) {
        const int stage = chunk & 1;
        const uint32_t s0 = sb + stage * MAT2_STAGE;
#pragma unroll
        for (int j = 0; j < 4; j++) {
            int idx = tid + 256 * j;          // 0..1023
            int mat = idx >> 9;               // 0=A,1=B
            int wi  = idx & 511;
            int row = wi >> 2;
            int c   = wi & 3;
            const __half* gp = (mat == 0) ? A + (size_t)(m0 + row) * IDIM
                                          : B + (size_t)(n0 + row) * IDIM;
            cp_async16(s0 + mat * MAT_BYTES + row * RS + c * 16,
                       gp + chunk * GBK + c * 8);
        }
    };

    float acc[4][4][4];
#pragma unroll
    for (int mi = 0; mi < 4; mi++)
#pragma unroll
        for (int ni = 0; ni < 4; ni++)
#pragma unroll
            for (int r = 0; r < 4; r++) acc[mi][ni][r] = 0.0f;

    const uint32_t a_row = wm * 64 + (lane & 15);
    const uint32_t b_row = wn * 32 + (lane & 15);
    const uint32_t colb  = (lane >> 4) * 16;

    issue_loads(0); CP_COMMIT();

    for (int i = 0; i < NCHUNK; i++) {
        const int stage = i & 1;
        if (i + 1 < NCHUNK) { issue_loads(i + 1); CP_COMMIT(); CP_WAIT1(); }
        else                { CP_WAIT0(); }
        __syncthreads();

        const uint32_t sA = sb + stage * MAT2_STAGE;
        const uint32_t sB = sA + MAT_BYTES;

#pragma unroll
        for (int ks = 0; ks < 2; ks++) {
            const uint32_t kb = ks * 32 + colb;
            uint32_t a[4][4], b[2][4];
#pragma unroll
            for (int mi = 0; mi < 4; mi++)
                ldsm_x4(a[mi], sA + (a_row + mi * 16) * RS + kb);
#pragma unroll
            for (int nt = 0; nt < 2; nt++)
                ldsm_x4(b[nt], sB + (b_row + nt * 16) * RS + kb);
#pragma unroll
            for (int mi = 0; mi < 4; mi++) {
#pragma unroll
                for (int ni = 0; ni < 4; ni++) {
                    const int nt = ni >> 1, sub = ni & 1;
                    mma16816h(acc[mi][ni], a[mi], b[nt][sub], b[nt][2 + sub]);
                }
            }
        }
        __syncthreads();
    }

    const int er = lane >> 2;
    const int ec = (lane & 3) * 2;
#pragma unroll
    for (int mi = 0; mi < 4; mi++) {
#pragma unroll
        for (int ni = 0; ni < 4; ni++) {
            int row = m0 + wm * 64 + mi * 16 + er;
            int col = n0 + wn * 32 + ni * 8 + ec;
            *reinterpret_cast<float2*>(&C[(size_t)row * N + col]) =
                make_float2(acc[mi][ni][0], acc[mi][ni][1]);
            *reinterpret_cast<float2*>(&C[(size_t)(row + 8) * N + col]) =
                make_float2(acc[mi][ni][2], acc[mi][ni][3]);
        }
    }
}

// ---------------- warp-per-row RMSNorm + RoPE for Q (+ gate fp16) ----------------
// 8 warps/block, each warp one (l,h) row: 8 elems/lane, shuffle-only reduction.
__global__ __launch_bounds__(256) void qnorm_rope_kernel(
    const float* __restrict__ cosb, const float* __restrict__ sinb,
    const float* __restrict__ gamma)
{
    const int ridx = blockIdx.x * 8 + (threadIdx.x >> 5);  // 0..32767
    const int lane = threadIdx.x & 31;
    const int l = ridx >> 3, h = ridx & 7;
    const float* row = g_qraw + (size_t)l * (ODIM * 2) + h * 512;

    float4 a = *reinterpret_cast<const float4*>(row + lane * 8);
    float4 b = *reinterpret_cast<const float4*>(row + lane * 8 + 4);
    float y[8] = {a.x, a.y, a.z, a.w, b.x, b.y, b.z, b.w};

    float s = 0.0f;
#pragma unroll
    for (int j = 0; j < 8; j++) s += y[j] * y[j];
#pragma unroll
    for (int o = 16; o > 0; o >>= 1) s += __shfl_xor_sync(0xffffffffu, s, o);
    float rstd = rsqrtf(s * (1.0f / 256.0f) + 1e-6f);

    float4 ga = *reinterpret_cast<const float4*>(gamma + lane * 8);
    float4 gb = *reinterpret_cast<const float4*>(gamma + lane * 8 + 4);
    float gm[8] = {ga.x, ga.y, ga.z, ga.w, gb.x, gb.y, gb.z, gb.w};
#pragma unroll
    for (int j = 0; j < 8; j++) y[j] *= rstd * gm[j];

    // RoPE on d<64 (lanes 0..7); partner d±32 = shfl_xor lane 4
    float oth[8];
#pragma unroll
    for (int j = 0; j < 8; j++) oth[j] = __shfl_xor_sync(0xffffffffu, y[j], 4);
    if (lane < 8) {
        const float* cb  = cosb + (size_t)l * ROPED + lane * 8;
        const float* sbp = sinb + (size_t)l * ROPED + lane * 8;
#pragma unroll
        for (int j = 0; j < 8; j++) {
            float rot = (lane < 4) ? -oth[j] : oth[j];
            y[j] = y[j] * cb[j] + rot * sbp[j];
        }
    }

    float4 g0 = *reinterpret_cast<const float4*>(row + 256 + lane * 8);
    float4 g1 = *reinterpret_cast<const float4*>(row + 256 + lane * 8 + 4);
    float gv[8] = {g0.x, g0.y, g0.z, g0.w, g1.x, g1.y, g1.z, g1.w};

    size_t o = (size_t)l * ODIM + h * HDIM + lane * 8;
    uint32_t qw[4], gw[4];
#pragma unroll
    for (int j = 0; j < 4; j++) {
        qw[j] = pack_h2(__float2half_rn(y[j*2] * QSCALE), __float2half_rn(y[j*2+1] * QSCALE));
        gw[j] = pack_h2(__float2half_rn(gv[j*2]), __float2half_rn(gv[j*2+1]));
    }
    *reinterpret_cast<uint4*>(&g_q16[o])    = make_uint4(qw[0], qw[1], qw[2], qw[3]);
    *reinterpret_cast<uint4*>(&g_gate16[o]) = make_uint4(gw[0], gw[1], gw[2], gw[3]);
}

// ---------------- warp-per-row RMSNorm + RoPE for K + V cast ----------------
__global__ __launch_bounds__(256) void knorm_rope_v_kernel(
    const float* __restrict__ cosb, const float* __restrict__ sinb,
    const float* __restrict__ gamma)
{
    const int ridx = blockIdx.x * 8 + (threadIdx.x >> 5);  // 0..8191
    const int lane = threadIdx.x & 31;
    const int l = ridx >> 1, g = ridx & 1;
    const float* krow = g_kvraw + (size_t)l * 1024 + g * HDIM;
    const float* vrow = g_kvraw + (size_t)l * 1024 + 512 + g * HDIM;

    float4 a = *reinterpret_cast<const float4*>(krow + lane * 8);
    float4 b = *reinterpret_cast<const float4*>(krow + lane * 8 + 4);
    float y[8] = {a.x, a.y, a.z, a.w, b.x, b.y, b.z, b.w};

    float s = 0.0f;
#pragma unroll
    for (int j = 0; j < 8; j++) s += y[j] * y[j];
#pragma unroll
    for (int o = 16; o > 0; o >>= 1) s += __shfl_xor_sync(0xffffffffu, s, o);
    float rstd = rsqrtf(s * (1.0f / 256.0f) + 1e-6f);

    float4 ga = *reinterpret_cast<const float4*>(gamma + lane * 8);
    float4 gb = *reinterpret_cast<const float4*>(gamma + lane * 8 + 4);
    float gm[8] = {ga.x, ga.y, ga.z, ga.w, gb.x, gb.y, gb.z, gb.w};
#pragma unroll
    for (int j = 0; j < 8; j++) y[j] *= rstd * gm[j];

    float oth[8];
#pragma unroll
    for (int j = 0; j < 8; j++) oth[j] = __shfl_xor_sync(0xffffffffu, y[j], 4);
    if (lane < 8) {
        const float* cb  = cosb + (size_t)l * ROPED + lane * 8;
        const float* sbp = sinb + (size_t)l * ROPED + lane * 8;
#pragma unroll
        for (int j = 0; j < 8; j++) {
            float rot = (lane < 4) ? -oth[j] : oth[j];
            y[j] = y[j] * cb[j] + rot * sbp[j];
        }
    }

    float4 v0 = *reinterpret_cast<const float4*>(vrow + lane * 8);
    float4 v1 = *reinterpret_cast<const float4*>(vrow + lane * 8 + 4);
    float vv[8] = {v0.x, v0.y, v0.z, v0.w, v1.x, v1.y, v1.z, v1.w};

    size_t o = (size_t)l * NKV + g * HDIM + lane * 8;
    uint32_t kw[4], vw[4];
#pragma unroll
    for (int j = 0; j < 4; j++) {
        kw[j] = pack_h2(__float2half_rn(y[j*2]), __float2half_rn(y[j*2+1]));
        vw[j] = pack_h2(__float2half_rn(vv[j*2]), __float2half_rn(vv[j*2+1]));
    }
    *reinterpret_cast<uint4*>(&g_k16[o]) = make_uint4(kw[0], kw[1], kw[2], kw[3]);
    *reinterpret_cast<uint4*>(&g_v16[o]) = make_uint4(vw[0], vw[1], vw[2], vw[3]);
}

// ---------------- MMA flash attention (single fp16), BR=BC=64, D=256 ----------------
#define AQ   0
#define AK   32768
#define AV   65536
#define AP   98304                  // 64 x 128B (fp16 P, swizzled)
#define APM  (AP + 8192)            // partial max: 2 x 64 floats
#define APS  (APM + 512)            // partial sum: 2 x 64 floats
#define AMR  (APS + 512)
#define ALR  (AMR + 256)
#define ACR  (ALR + 256)
#define ATT_SMEM (ACR + 256)        // 108288

__device__ __forceinline__ uint32_t sw512(int row, int g) {
    return (uint32_t)(row * 512 + ((g ^ (row & 7)) << 4));
}
__device__ __forceinline__ uint32_t sw128(int row, int g) {
    return (uint32_t)(row * 128 + ((g ^ (row & 7)) << 4));
}

__global__ __launch_bounds__(256, 2) void attn_mma_kernel()
{
    extern __shared__ char sm[];
    const uint32_t sb = smem_to_u32(sm);
    const int tid  = threadIdx.x;
    const int lane = tid & 31;
    const int wid  = tid >> 5;
    const int qt   = gridDim.x - 1 - blockIdx.x;   // big tiles first
    const int h    = blockIdx.y;
    const int g    = h >> 2;
    const int i0   = qt * 64;

    float* pmax = reinterpret_cast<float*>(sm + APM);
    float* psum = reinterpret_cast<float*>(sm + APS);
    float* mrow = reinterpret_cast<float*>(sm + AMR);
    float* lrow = reinterpret_cast<float*>(sm + ALR);
    float* crow = reinterpret_cast<float*>(sm + ACR);

    auto load_k = [&](int j0) {
        const size_t rbase = ((size_t)j0 * NGROUPS + g) * HDIM;
        const size_t rstr  = (size_t)NGROUPS * HDIM;
#pragma unroll
        for (int i = 0; i < 8; i++) {
            int idx = tid + 256 * i;
            int row = idx >> 5, gr = idx & 31;
            cp_async16(sb + AK + sw512(row, gr),
                       (const char*)g_k16 + (rbase + (size_t)row * rstr) * 2 + gr * 16);
        }
    };
    auto load_v = [&](int j0) {
        const size_t rbase = ((size_t)j0 * NGROUPS + g) * HDIM;
        const size_t rstr  = (size_t)NGROUPS * HDIM;
#pragma unroll
        for (int i = 0; i < 8; i++) {
            int idx = tid + 256 * i;
            int row = idx >> 5, gr = idx & 31;
            cp_async16(sb + AV + sw512(row, gr),
                       (const char*)g_v16 + (rbase + (size_t)row * rstr) * 2 + gr * 16);
        }
    };

    // ---- prolog: Q, K(0), V(0) ----
    {
        const char* q16 = (const char*)(g_q16 + ((size_t)i0 * NHEADS + h) * HDIM);
        const size_t rstr = (size_t)NHEADS * HDIM * 2;
#pragma unroll
        for (int i = 0; i < 8; i++) {
            int idx = tid + 256 * i;
            int row = idx >> 5, gr = idx & 31;
            cp_async16(sb + AQ + sw512(row, gr), q16 + (size_t)row * rstr + gr * 16);
        }
    }
    CP_COMMIT();
    load_k(0); CP_COMMIT();
    if (tid < 64) { mrow[tid] = -INFINITY; lrow[tid] = 0.0f; }
    load_v(0); CP_COMMIT();

    const int wm = wid & 3;
    const int wn = wid >> 2;
    const int er = lane >> 2;
    const int ec = (lane & 3) * 2;
    const int kgl = lane >> 4;

    float oacc[16][4];
#pragma unroll
    for (int t = 0; t < 16; t++)
#pragma unroll
        for (int r = 0; r < 4; r++) oacc[t][r] = 0.0f;

    for (int j0 = 0; j0 <= i0; j0 += 64) {
        CP_WAIT1();                // Q (+K) ready
        __syncthreads();

        // ---- S = Q K^T ----
        float sacc[4][4];
#pragma unroll
        for (int t = 0; t < 4; t++)
#pragma unroll
            for (int r = 0; r < 4; r++) sacc[t][r] = 0.0f;

        const int arow  = wm * 16 + (lane & 15);
        const int brow0 = wn * 32 + (lane & 15);
#pragma unroll 4
        for (int ks = 0; ks < 16; ks++) {
            int kg = ks * 2 + kgl;
            uint32_t a[4], b[2][4];
            ldsm_x4(a, sb + AQ + sw512(arow, kg));
            ldsm_x4(b[0], sb + AK + sw512(brow0, kg));
            ldsm_x4(b[1], sb + AK + sw512(brow0 + 16, kg));
#pragma unroll
            for (int nt = 0; nt < 2; nt++)
#pragma unroll
                for (int sub = 0; sub < 2; sub++)
                    mma16816h(sacc[nt * 2 + sub], a, b[nt][sub], b[nt][2 + sub]);
        }

        // ---- fused softmax (register-resident) ----
        const int r0 = wm * 16 + er;
        const int r1 = r0 + 8;
        {
            const int lim0 = i0 + r0 - j0;
            const int lim1 = lim0 + 8;
            float m0 = -INFINITY, m1 = -INFINITY;
#pragma unroll
            for (int t = 0; t < 4; t++) {
                int col = wn * 32 + (t >> 1) * 16 + (t & 1) * 8 + ec;
                if (col > lim0)     sacc[t][0] = -INFINITY;
                if (col + 1 > lim0) sacc[t][1] = -INFINITY;
                if (col > lim1)     sacc[t][2] = -INFINITY;
                if (col + 1 > lim1) sacc[t][3] = -INFINITY;
                m0 = fmaxf(m0, fmaxf(sacc[t][0], sacc[t][1]));
                m1 = fmaxf(m1, fmaxf(sacc[t][2], sacc[t][3]));
            }
            m0 = fmaxf(m0, __shfl_xor_sync(0xffffffffu, m0, 1));
            m0 = fmaxf(m0, __shfl_xor_sync(0xffffffffu, m0, 2));
            m1 = fmaxf(m1, __shfl_xor_sync(0xffffffffu, m1, 1));
            m1 = fmaxf(m1, __shfl_xor_sync(0xffffffffu, m1, 2));
            if ((lane & 3) == 0) { pmax[wn * 64 + r0] = m0; pmax[wn * 64 + r1] = m1; }
            __syncthreads();

            float mn0 = fmaxf(fmaxf(pmax[r0], pmax[64 + r0]), mrow[r0]);
            float mn1 = fmaxf(fmaxf(pmax[r1], pmax[64 + r1]), mrow[r1]);
            float s0 = 0.0f, s1 = 0.0f;
            uint32_t pw0[4], pw1[4];
#pragma unroll
            for (int t = 0; t < 4; t++) {
                float p00 = __expf(sacc[t][0] - mn0);
                float p01 = __expf(sacc[t][1] - mn0);
                float p10 = __expf(sacc[t][2] - mn1);
                float p11 = __expf(sacc[t][3] - mn1);
                s0 += p00 + p01; s1 += p10 + p11;
                pw0[t] = pack_h2(__float2half_rn(p00), __float2half_rn(p01));
                pw1[t] = pack_h2(__float2half_rn(p10), __float2half_rn(p11));
            }
            s0 += __shfl_xor_sync(0xffffffffu, s0, 1);
            s0 += __shfl_xor_sync(0xffffffffu, s0, 2);
            s1 += __shfl_xor_sync(0xffffffffu, s1, 1);
            s1 += __shfl_xor_sync(0xffffffffu, s1, 2);
#pragma unroll
            for (int t = 0; t < 4; t++) {
                int gidx = wn * 4 + (t >> 1) * 2 + (t & 1);
                *reinterpret_cast<uint32_t*>(sm + AP + sw128(r0, gidx) + (lane & 3) * 4) = pw0[t];
                *reinterpret_cast<uint32_t*>(sm + AP + sw128(r1, gidx) + (lane & 3) * 4) = pw1[t];
            }
            if ((lane & 3) == 0) { psum[wn * 64 + r0] = s0; psum[wn * 64 + r1] = s1; }
            __syncthreads();

            if (tid < 64) {
                float mold = mrow[tid];
                float mnew = fmaxf(fmaxf(pmax[tid], pmax[64 + tid]), mold);
                float corr = __expf(mold - mnew);
                lrow[tid] = lrow[tid] * corr + psum[tid] + psum[64 + tid];
                mrow[tid] = mnew;
                crow[tid] = corr;
            }
        }

        if (j0 + 64 <= i0) load_k(j0 + 64);
        CP_COMMIT();
        CP_WAIT1();               // V(j0) ready
        __syncthreads();          // also publishes crow/lrow updates

        // ---- rescale O, then O += P V ----
        {
            float c0 = crow[r0];
            float c1 = crow[r1];
#pragma unroll
            for (int t = 0; t < 16; t++) {
                oacc[t][0] *= c0; oacc[t][1] *= c0;
                oacc[t][2] *= c1; oacc[t][3] *= c1;
            }
        }
        const int prow = wm * 16 + (lane & 15);
        const int vk   = lane & 15;
        const int vng  = lane >> 4;
#pragma unroll
        for (int ks = 0; ks < 4; ks++) {
            uint32_t a[4];
            ldsm_x4(a, sb + AP + sw128(prow, ks * 2 + kgl));
            int krow = ks * 16 + vk;
#pragma unroll
            for (int ng = 0; ng < 8; ng++) {
                uint32_t vv[4];
                int gv = wn * 16 + ng * 2 + vng;
                ldsm_x4_trans(vv, sb + AV + sw512(krow, gv));
#pragma unroll
                for (int sub = 0; sub < 2; sub++)
                    mma16816h(oacc[ng * 2 + sub], a, vv[2 * sub], vv[2 * sub + 1]);
            }
        }
        __syncthreads();          // V buffer dead

        if (j0 + 64 <= i0) load_v(j0 + 64);
        CP_COMMIT();
    }

    // ---- epilogue: 1/l, sigmoid gate (fp16), write single fp16 y ----
    {
        const int r0 = wm * 16 + er;
        const float li0 = 1.0f / lrow[r0];
        const float li1 = 1.0f / lrow[r0 + 8];
        const size_t base0 = (size_t)(i0 + r0) * ODIM + h * HDIM;
        const size_t base1 = (size_t)(i0 + r0 + 8) * ODIM + h * HDIM;
#pragma unroll
        for (int t = 0; t < 16; t++) {
            int col = wn * 128 + (t >> 1) * 16 + (t & 1) * 8 + ec;
            __half2 gh0 = *reinterpret_cast<const __half2*>(&g_gate16[base0 + col]);
            __half2 gh1 = *reinterpret_cast<const __half2*>(&g_gate16[base1 + col]);
            float2 gt0 = __half22float2(gh0);
            float2 gt1 = __half22float2(gh1);
            float v00 = oacc[t][0] * li0 * (1.0f / (1.0f + __expf(-gt0.x)));
            float v01 = oacc[t][1] * li0 * (1.0f / (1.0f + __expf(-gt0.y)));
            float v10 = oacc[t][2] * li1 * (1.0f / (1.0f + __expf(-gt1.x)));
            float v11 = oacc[t][3] * li1 * (1.0f / (1.0f + __expf(-gt1.y)));
            *reinterpret_cast<__half2*>(&g_y[base0 + col]) =
                __halves2half2(__float2half_rn(v00), __float2half_rn(v01));
            *reinterpret_cast<__half2*>(&g_y[base1 + col]) =
                __halves2half2(__float2half_rn(v10), __float2half_rn(v11));
        }
    }
}

// ---------------- launch ----------------
extern "C" void kernel_launch(void* const* d_in, const int* in_sizes, int n_in,
                              void* d_out, int out_size)
{
    const float* x    = (const float*)d_in[0];
    const float* cosb = (const float*)d_in[1];
    const float* sinb = (const float*)d_in[2];
    const float* wq   = (const float*)d_in[4];
    const float* wk   = (const float*)d_in[5];
    const float* wv   = (const float*)d_in[6];
    const float* wo   = (const float*)d_in[7];
    const float* qg   = (const float*)d_in[8];
    const float* kg   = (const float*)d_in[9];
    float* out        = (float*)d_out;

    float *p_qraw, *p_kvraw;
    cudaGetSymbolAddress((void**)&p_qraw,  g_qraw);
    cudaGetSymbolAddress((void**)&p_kvraw, g_kvraw);

    __half *p_x16, *p_wq16, *p_wkv16, *p_wo16, *p_y;
    cudaGetSymbolAddress((void**)&p_x16,   g_x16);
    cudaGetSymbolAddress((void**)&p_wq16,  g_wq16);
    cudaGetSymbolAddress((void**)&p_wkv16, g_wkv16);
    cudaGetSymbolAddress((void**)&p_wo16,  g_wo16);
    cudaGetSymbolAddress((void**)&p_y,     g_y);

    cudaFuncSetAttribute(mma_gemmh, cudaFuncAttributeMaxDynamicSharedMemorySize, GEMM1_SMEM);
    cudaFuncSetAttribute(attn_mma_kernel, cudaFuncAttributeMaxDynamicSharedMemorySize, ATT_SMEM);

    // 0) operand prep (all fp16, 1-term)
    cast_h_kernel<<<2048, 256>>>(x, p_x16, (size_t)L_SEQ * IDIM / 4);
    transpose_h_kernel<<<dim3((ODIM*2)/32, IDIM/32), 256>>>(wq, p_wq16, IDIM, ODIM*2);
    transpose_h_kernel<<<dim3(NKV/32, IDIM/32), 256>>>(wk, p_wkv16, IDIM, NKV);
    transpose_h_kernel<<<dim3(NKV/32, IDIM/32), 256>>>(
        wv, p_wkv16 + (size_t)512 * IDIM, IDIM, NKV);
    transpose_h_kernel<<<dim3(IDIM/32, ODIM/32), 256>>>(wo, p_wo16, ODIM, IDIM);

    // 1) projections: Q (N=4096) and fused KV (N=1024), 1-term fp16 (proven R12 structure)
    mma_gemmh<<<dim3((ODIM*2)/128, L_SEQ/128), 256, GEMM1_SMEM>>>(p_x16, p_wq16, p_qraw, ODIM*2);
    mma_gemmh<<<dim3(1024/128,     L_SEQ/128), 256, GEMM1_SMEM>>>(p_x16, p_wkv16, p_kvraw, 1024);

    // 2) warp-per-row norms + RoPE -> single fp16
    qnorm_rope_kernel<<<L_SEQ * NHEADS / 8,  256>>>(cosb, sinb, qg);
    knorm_rope_v_kernel<<<L_SEQ * NGROUPS / 8, 256>>>(cosb, sinb, kg);

    // 3) MMA flash attention (fused register softmax, 2 CTAs/SM) -> fp16 y
    attn_mma_kernel<<<dim3(L_SEQ / 64, NHEADS), 256, ATT_SMEM>>>();

    // 4) output projection: 1-term fp16
    mma_gemmh<<<dim3(IDIM/128, L_SEQ/128), 256, GEMM1_SMEM>>>(p_y, p_wo16, out, IDIM);
}

// round 15
// speedup vs baseline: 1.5573x; 1.0221x over previous
#include <cuda_runtime.h>
#include <cuda_bf16.h>
#include <cuda_fp16.h>
#include <math.h>
#include <stdint.h>

// ---------------- problem constants ----------------
#define L_SEQ   4096
#define IDIM    2048
#define NHEADS  8
#define NGROUPS 2
#define HDIM    256
#define ROPED   64
#define ODIM    (NHEADS*HDIM)     // 2048
#define NKV     (NGROUPS*HDIM)    // 512
#define QSCALE  0.0625f           // 256^-0.5

// ---------------- warp-MMA helpers (standard PTX, sm_80+) ----------------
__device__ __forceinline__ void ldsm_x4(uint32_t* r, uint32_t addr) {
    asm volatile("ldmatrix.sync.aligned.m8n8.x4.shared.b16 {%0,%1,%2,%3}, [%4];"
        : "=r"(r[0]), "=r"(r[1]), "=r"(r[2]), "=r"(r[3]) : "r"(addr));
}
__device__ __forceinline__ void ldsm_x4_trans(uint32_t* r, uint32_t addr) {
    asm volatile("ldmatrix.sync.aligned.m8n8.x4.trans.shared.b16 {%0,%1,%2,%3}, [%4];"
        : "=r"(r[0]), "=r"(r[1]), "=r"(r[2]), "=r"(r[3]) : "r"(addr));
}
__device__ __forceinline__ void mma16816h(float* d, const uint32_t* a, uint32_t b0, uint32_t b1) {
    asm volatile("mma.sync.aligned.m16n8k16.row.col.f32.f16.f16.f32 "
        "{%0,%1,%2,%3}, {%4,%5,%6,%7}, {%8,%9}, {%0,%1,%2,%3};"
        : "+f"(d[0]), "+f"(d[1]), "+f"(d[2]), "+f"(d[3])
        : "r"(a[0]), "r"(a[1]), "r"(a[2]), "r"(a[3]), "r"(b0), "r"(b1));
}
__device__ __forceinline__ void cp_async16(uint32_t dst, const void* src) {
    asm volatile("cp.async.cg.shared.global [%0], [%1], 16;" :: "r"(dst), "l"(src));
}
#define CP_COMMIT() asm volatile("cp.async.commit_group;" ::: "memory")
#define CP_WAIT1()  asm volatile("cp.async.wait_group 1;" ::: "memory")
#define CP_WAIT0()  asm volatile("cp.async.wait_group 0;" ::: "memory")

__device__ __forceinline__ uint32_t smem_to_u32(const void* p) {
    uint32_t a;
    asm("{ .reg .u64 t; cvta.to.shared.u64 t, %1; cvt.u32.u64 %0, t; }" : "=r"(a) : "l"(p));
    return a;
}
__device__ __forceinline__ uint32_t pack_h2(__half a, __half b) {
    __half2 t = __halves2half2(a, b);
    return *reinterpret_cast<uint32_t*>(&t);
}

// ---------------- scratch (device globals) ----------------
__device__ float  g_qraw [(size_t)L_SEQ * (ODIM*2)];
__device__ __half g_gate16[(size_t)L_SEQ * ODIM];
__device__ float  g_kvraw[(size_t)L_SEQ * 1024];    // cols 0-511 = K, 512-1023 = V

// fp16 operands (all GEMMs 1-term fp16)
__device__ __half g_x16  [(size_t)L_SEQ * IDIM];
__device__ __half g_wq16 [(size_t)(ODIM*2) * IDIM];
__device__ __half g_wkv16[(size_t)1024 * IDIM];     // rows 0-511 wk^T, 512-1023 wv^T
__device__ __half g_wo16 [(size_t)IDIM * ODIM];
__device__ __half g_y    [(size_t)L_SEQ * ODIM];
// attention operands (single fp16)
__device__ __half g_q16 [(size_t)L_SEQ * ODIM];     // pre-scaled
__device__ __half g_k16 [(size_t)L_SEQ * NKV];
__device__ __half g_v16 [(size_t)L_SEQ * NKV];
// split-KV partials: 512 pieces (qt 32..63 x 8 heads x 2 halves), 64 rows x 256 cols
__device__ float g_opart[(size_t)512 * 64 * 256];
__device__ float g_mpart[(size_t)512 * 64];
__device__ float g_lpart[(size_t)512 * 64];

// ---------------- cast kernel: fp32 -> fp16 ----------------
__global__ __launch_bounds__(256) void cast_h_kernel(
    const float* __restrict__ in, __half* __restrict__ out, size_t n4)
{
    size_t i = (size_t)blockIdx.x * blockDim.x + threadIdx.x;
    size_t stride = (size_t)gridDim.x * blockDim.x;
    for (; i < n4; i += stride) {
        float4 v = reinterpret_cast<const float4*>(in)[i];
        __half2 a = __halves2half2(__float2half_rn(v.x), __float2half_rn(v.y));
        __half2 b = __halves2half2(__float2half_rn(v.z), __float2half_rn(v.w));
        reinterpret_cast<__half2*>(out)[i*2]   = a;
        reinterpret_cast<__half2*>(out)[i*2+1] = b;
    }
}

// ---------------- transpose: W[K][N] fp32 -> Wt [N][K] fp16 ----------------
__global__ __launch_bounds__(256) void transpose_h_kernel(
    const float* __restrict__ W, __half* __restrict__ T, int Kdim, int Ndim)
{
    __shared__ float tile[32][33];
    int n0 = blockIdx.x * 32;
    int k0 = blockIdx.y * 32;
    int tx = threadIdx.x & 31;
    int ty = threadIdx.x >> 5;
#pragma unroll
    for (int r = 0; r < 4; r++)
        tile[ty + 8*r][tx] = W[(size_t)(k0 + ty + 8*r) * Ndim + n0 + tx];
    __syncthreads();
#pragma unroll
    for (int r = 0; r < 4; r++) {
        float v = tile[tx][ty + 8*r];
        T[(size_t)(n0 + ty + 8*r) * Kdim + k0 + tx] = __float2half_rn(v);
    }
}

// ---------------- 1-term fp16 GEMM: C = A(fp16) @ B(fp16)^T ----------------
#define GBK 32
#define NCHUNK (IDIM / GBK)            // 64
#define RS 80                          // smem row stride bytes
#define MAT_BYTES (128 * RS)           // 10240
#define MAT2_STAGE (2 * MAT_BYTES)     // 20480
#define GEMM1_SMEM (2 * MAT2_STAGE)    // 40960

__global__ __launch_bounds__(256) void mma_gemmh(
    const __half* __restrict__ A, const __half* __restrict__ B,
    float* __restrict__ C, int N)
{
    extern __shared__ char smem[];
    const uint32_t sb = smem_to_u32(smem);

    const int tid  = threadIdx.x;
    const int lane = tid & 31;
    const int wid  = tid >> 5;
    const int wm   = wid & 1;
    const int wn   = wid >> 1;
    const int m0   = blockIdx.y * 128;
    const int n0   = blockIdx.x * 128;

    auto issue_loads = [&](int chunk) {
        const int stage = chunk & 1;
        const uint32_t s0 = sb + stage * MAT2_STAGE;
#pragma unroll
        for (int j = 0; j < 4; j++) {
            int idx = tid + 256 * j;          // 0..1023
            int mat = idx >> 9;               // 0=A,1=B
            int wi  = idx & 511;
            int row = wi >> 2;
            int c   = wi & 3;
            const __half* gp = (mat == 0) ? A + (size_t)(m0 + row) * IDIM
                                          : B + (size_t)(n0 + row) * IDIM;
            cp_async16(s0 + mat * MAT_BYTES + row * RS + c * 16,
                       gp + chunk * GBK + c * 8);
        }
    };

    float acc[4][4][4];
#pragma unroll
    for (int mi = 0; mi < 4; mi++)
#pragma unroll
        for (int ni = 0; ni < 4; ni++)
#pragma unroll
            for (int r = 0; r < 4; r++) acc[mi][ni][r] = 0.0f;

    const uint32_t a_row = wm * 64 + (lane & 15);
    const uint32_t b_row = wn * 32 + (lane & 15);
    const uint32_t colb  = (lane >> 4) * 16;

    issue_loads(0); CP_COMMIT();

    for (int i = 0; i < NCHUNK; i++) {
        const int stage = i & 1;
        if (i + 1 < NCHUNK) { issue_loads(i + 1); CP_COMMIT(); CP_WAIT1(); }
        else                { CP_WAIT0(); }
        __syncthreads();

        const uint32_t sA = sb + stage * MAT2_STAGE;
        const uint32_t sB = sA + MAT_BYTES;

#pragma unroll
        for (int ks = 0; ks < 2; ks++) {
            const uint32_t kb = ks * 32 + colb;
            uint32_t a[4][4], b[2][4];
#pragma unroll
            for (int mi = 0; mi < 4; mi++)
                ldsm_x4(a[mi], sA + (a_row + mi * 16) * RS + kb);
#pragma unroll
            for (int nt = 0; nt < 2; nt++)
                ldsm_x4(b[nt], sB + (b_row + nt * 16) * RS + kb);
#pragma unroll
            for (int mi = 0; mi < 4; mi++) {
#pragma unroll
                for (int ni = 0; ni < 4; ni++) {
                    const int nt = ni >> 1, sub = ni & 1;
                    mma16816h(acc[mi][ni], a[mi], b[nt][sub], b[nt][2 + sub]);
                }
            }
        }
        __syncthreads();
    }

    const int er = lane >> 2;
    const int ec = (lane & 3) * 2;
#pragma unroll
    for (int mi = 0; mi < 4; mi++) {
#pragma unroll
        for (int ni = 0; ni < 4; ni++) {
            int row = m0 + wm * 64 + mi * 16 + er;
            int col = n0 + wn * 32 + ni * 8 + ec;
            *reinterpret_cast<float2*>(&C[(size_t)row * N + col]) =
                make_float2(acc[mi][ni][0], acc[mi][ni][1]);
            *reinterpret_cast<float2*>(&C[(size_t)(row + 8) * N + col]) =
                make_float2(acc[mi][ni][2], acc[mi][ni][3]);
        }
    }
}

// ---------------- warp-per-row RMSNorm + RoPE for Q (+ gate fp16) ----------------
__global__ __launch_bounds__(256) void qnorm_rope_kernel(
    const float* __restrict__ cosb, const float* __restrict__ sinb,
    const float* __restrict__ gamma)
{
    const int ridx = blockIdx.x * 8 + (threadIdx.x >> 5);  // 0..32767
    const int lane = threadIdx.x & 31;
    const int l = ridx >> 3, h = ridx & 7;
    const float* row = g_qraw + (size_t)l * (ODIM * 2) + h * 512;

    float4 a = *reinterpret_cast<const float4*>(row + lane * 8);
    float4 b = *reinterpret_cast<const float4*>(row + lane * 8 + 4);
    float y[8] = {a.x, a.y, a.z, a.w, b.x, b.y, b.z, b.w};

    float s = 0.0f;
#pragma unroll
    for (int j = 0; j < 8; j++) s += y[j] * y[j];
#pragma unroll
    for (int o = 16; o > 0; o >>= 1) s += __shfl_xor_sync(0xffffffffu, s, o);
    float rstd = rsqrtf(s * (1.0f / 256.0f) + 1e-6f);

    float4 ga = *reinterpret_cast<const float4*>(gamma + lane * 8);
    float4 gb = *reinterpret_cast<const float4*>(gamma + lane * 8 + 4);
    float gm[8] = {ga.x, ga.y, ga.z, ga.w, gb.x, gb.y, gb.z, gb.w};
#pragma unroll
    for (int j = 0; j < 8; j++) y[j] *= rstd * gm[j];

    float oth[8];
#pragma unroll
    for (int j = 0; j < 8; j++) oth[j] = __shfl_xor_sync(0xffffffffu, y[j], 4);
    if (lane < 8) {
        const float* cb  = cosb + (size_t)l * ROPED + lane * 8;
        const float* sbp = sinb + (size_t)l * ROPED + lane * 8;
#pragma unroll
        for (int j = 0; j < 8; j++) {
            float rot = (lane < 4) ? -oth[j] : oth[j];
            y[j] = y[j] * cb[j] + rot * sbp[j];
        }
    }

    float4 g0 = *reinterpret_cast<const float4*>(row + 256 + lane * 8);
    float4 g1 = *reinterpret_cast<const float4*>(row + 256 + lane * 8 + 4);
    float gv[8] = {g0.x, g0.y, g0.z, g0.w, g1.x, g1.y, g1.z, g1.w};

    size_t o = (size_t)l * ODIM + h * HDIM + lane * 8;
    uint32_t qw[4], gw[4];
#pragma unroll
    for (int j = 0; j < 4; j++) {
        qw[j] = pack_h2(__float2half_rn(y[j*2] * QSCALE), __float2half_rn(y[j*2+1] * QSCALE));
        gw[j] = pack_h2(__float2half_rn(gv[j*2]), __float2half_rn(gv[j*2+1]));
    }
    *reinterpret_cast<uint4*>(&g_q16[o])    = make_uint4(qw[0], qw[1], qw[2], qw[3]);
    *reinterpret_cast<uint4*>(&g_gate16[o]) = make_uint4(gw[0], gw[1], gw[2], gw[3]);
}

// ---------------- warp-per-row RMSNorm + RoPE for K + V cast ----------------
__global__ __launch_bounds__(256) void knorm_rope_v_kernel(
    const float* __restrict__ cosb, const float* __restrict__ sinb,
    const float* __restrict__ gamma)
{
    const int ridx = blockIdx.x * 8 + (threadIdx.x >> 5);  // 0..8191
    const int lane = threadIdx.x & 31;
    const int l = ridx >> 1, g = ridx & 1;
    const float* krow = g_kvraw + (size_t)l * 1024 + g * HDIM;
    const float* vrow = g_kvraw + (size_t)l * 1024 + 512 + g * HDIM;

    float4 a = *reinterpret_cast<const float4*>(krow + lane * 8);
    float4 b = *reinterpret_cast<const float4*>(krow + lane * 8 + 4);
    float y[8] = {a.x, a.y, a.z, a.w, b.x, b.y, b.z, b.w};

    float s = 0.0f;
#pragma unroll
    for (int j = 0; j < 8; j++) s += y[j] * y[j];
#pragma unroll
    for (int o = 16; o > 0; o >>= 1) s += __shfl_xor_sync(0xffffffffu, s, o);
    float rstd = rsqrtf(s * (1.0f / 256.0f) + 1e-6f);

    float4 ga = *reinterpret_cast<const float4*>(gamma + lane * 8);
    float4 gb = *reinterpret_cast<const float4*>(gamma + lane * 8 + 4);
    float gm[8] = {ga.x, ga.y, ga.z, ga.w, gb.x, gb.y, gb.z, gb.w};
#pragma unroll
    for (int j = 0; j < 8; j++) y[j] *= rstd * gm[j];

    float oth[8];
#pragma unroll
    for (int j = 0; j < 8; j++) oth[j] = __shfl_xor_sync(0xffffffffu, y[j], 4);
    if (lane < 8) {
        const float* cb  = cosb + (size_t)l * ROPED + lane * 8;
        const float* sbp = sinb + (size_t)l * ROPED + lane * 8;
#pragma unroll
        for (int j = 0; j < 8; j++) {
            float rot = (lane < 4) ? -oth[j] : oth[j];
            y[j] = y[j] * cb[j] + rot * sbp[j];
        }
    }

    float4 v0 = *reinterpret_cast<const float4*>(vrow + lane * 8);
    float4 v1 = *reinterpret_cast<const float4*>(vrow + lane * 8 + 4);
    float vv[8] = {v0.x, v0.y, v0.z, v0.w, v1.x, v1.y, v1.z, v1.w};

    size_t o = (size_t)l * NKV + g * HDIM + lane * 8;
    uint32_t kw[4], vw[4];
#pragma unroll
    for (int j = 0; j < 4; j++) {
        kw[j] = pack_h2(__float2half_rn(y[j*2]), __float2half_rn(y[j*2+1]));
        vw[j] = pack_h2(__float2half_rn(vv[j*2]), __float2half_rn(vv[j*2+1]));
    }
    *reinterpret_cast<uint4*>(&g_k16[o]) = make_uint4(kw[0], kw[1], kw[2], kw[3]);
    *reinterpret_cast<uint4*>(&g_v16[o]) = make_uint4(vw[0], vw[1], vw[2], vw[3]);
}

// ---------------- MMA flash attention, split-KV, BR=BC=64, D=256 ----------------
#define AQ   0
#define AK   32768
#define AV   65536
#define AP   98304
#define APM  (AP + 8192)
#define APS  (APM + 512)
#define AMR  (APS + 512)
#define ALR  (AMR + 256)
#define ACR  (ALR + 256)
#define ATT_SMEM (ACR + 256)        // 108288

__device__ __forceinline__ uint32_t sw512(int row, int g) {
    return (uint32_t)(row * 512 + ((g ^ (row & 7)) << 4));
}
__device__ __forceinline__ uint32_t sw128(int row, int g) {
    return (uint32_t)(row * 128 + ((g ^ (row & 7)) << 4));
}

// grid (96, 8): bx 0..63 = split pieces (qt = 63 - bx/2, half = bx&1);
//               bx 64..95 = full blocks (qt = 95 - bx, i.e. 31..0)
__global__ __launch_bounds__(256, 2) void attn_mma_kernel()
{
    extern __shared__ char sm[];
    const uint32_t sb = smem_to_u32(sm);
    const int tid  = threadIdx.x;
    const int lane = tid & 31;
    const int wid  = tid >> 5;
    const int bx   = blockIdx.x;
    const int h    = blockIdx.y;
    const int g    = h >> 2;

    int qt, jt0, jt1, half;
    bool is_split;
    if (bx < 64) {
        is_split = true;
        half = bx & 1;
        qt = 63 - (bx >> 1);
        int nt = qt + 1;
        int sp = nt >> 1;
        jt0 = half ? sp : 0;
        jt1 = half ? nt : sp;
    } else {
        is_split = false;
        half = 0;
        qt = 95 - bx;
        jt0 = 0;
        jt1 = qt + 1;
    }
    const int i0  = qt * 64;
    const int jlo = jt0 * 64;
    const int jhi = (jt1 - 1) * 64;      // last tile start

    float* pmax = reinterpret_cast<float*>(sm + APM);
    float* psum = reinterpret_cast<float*>(sm + APS);
    float* mrow = reinterpret_cast<float*>(sm + AMR);
    float* lrow = reinterpret_cast<float*>(sm + ALR);
    float* crow = reinterpret_cast<float*>(sm + ACR);

    auto load_k = [&](int j0) {
        const size_t rbase = ((size_t)j0 * NGROUPS + g) * HDIM;
        const size_t rstr  = (size_t)NGROUPS * HDIM;
#pragma unroll
        for (int i = 0; i < 8; i++) {
            int idx = tid + 256 * i;
            int row = idx >> 5, gr = idx & 31;
            cp_async16(sb + AK + sw512(row, gr),
                       (const char*)g_k16 + (rbase + (size_t)row * rstr) * 2 + gr * 16);
        }
    };
    auto load_v = [&](int j0) {
        const size_t rbase = ((size_t)j0 * NGROUPS + g) * HDIM;
        const size_t rstr  = (size_t)NGROUPS * HDIM;
#pragma unroll
        for (int i = 0; i < 8; i++) {
            int idx = tid + 256 * i;
            int row = idx >> 5, gr = idx & 31;
            cp_async16(sb + AV + sw512(row, gr),
                       (const char*)g_v16 + (rbase + (size_t)row * rstr) * 2 + gr * 16);
        }
    };

    // ---- prolog: Q, K(jlo), V(jlo) ----
    {
        const char* q16 = (const char*)(g_q16 + ((size_t)i0 * NHEADS + h) * HDIM);
        const size_t rstr = (size_t)NHEADS * HDIM * 2;
#pragma unroll
        for (int i = 0; i < 8; i++) {
            int idx = tid + 256 * i;
            int row = idx >> 5, gr = idx & 31;
            cp_async16(sb + AQ + sw512(row, gr), q16 + (size_t)row * rstr + gr * 16);
        }
    }
    CP_COMMIT();
    load_k(jlo); CP_COMMIT();
    if (tid < 64) { mrow[tid] = -INFINITY; lrow[tid] = 0.0f; }
    load_v(jlo); CP_COMMIT();

    const int wm = wid & 3;
    const int wn = wid >> 2;
    const int er = lane >> 2;
    const int ec = (lane & 3) * 2;
    const int kgl = lane >> 4;

    float oacc[16][4];
#pragma unroll
    for (int t = 0; t < 16; t++)
#pragma unroll
        for (int r = 0; r < 4; r++) oacc[t][r] = 0.0f;

    for (int j0 = jlo; j0 <= jhi; j0 += 64) {
        CP_WAIT1();
        __syncthreads();

        // ---- S = Q K^T ----
        float sacc[4][4];
#pragma unroll
        for (int t = 0; t < 4; t++)
#pragma unroll
            for (int r = 0; r < 4; r++) sacc[t][r] = 0.0f;

        const int arow  = wm * 16 + (lane & 15);
        const int brow0 = wn * 32 + (lane & 15);
#pragma unroll 4
        for (int ks = 0; ks < 16; ks++) {
            int kg = ks * 2 + kgl;
            uint32_t a[4], b[2][4];
            ldsm_x4(a, sb + AQ + sw512(arow, kg));
            ldsm_x4(b[0], sb + AK + sw512(brow0, kg));
            ldsm_x4(b[1], sb + AK + sw512(brow0 + 16, kg));
#pragma unroll
            for (int nt = 0; nt < 2; nt++)
#pragma unroll
                for (int sub = 0; sub < 2; sub++)
                    mma16816h(sacc[nt * 2 + sub], a, b[nt][sub], b[nt][2 + sub]);
        }

        // ---- fused softmax (register-resident) ----
        const int r0 = wm * 16 + er;
        const int r1 = r0 + 8;
        {
            const int lim0 = i0 + r0 - j0;
            const int lim1 = lim0 + 8;
            float m0 = -INFINITY, m1 = -INFINITY;
#pragma unroll
            for (int t = 0; t < 4; t++) {
                int col = wn * 32 + (t >> 1) * 16 + (t & 1) * 8 + ec;
                if (col > lim0)     sacc[t][0] = -INFINITY;
                if (col + 1 > lim0) sacc[t][1] = -INFINITY;
                if (col > lim1)     sacc[t][2] = -INFINITY;
                if (col + 1 > lim1) sacc[t][3] = -INFINITY;
                m0 = fmaxf(m0, fmaxf(sacc[t][0], sacc[t][1]));
                m1 = fmaxf(m1, fmaxf(sacc[t][2], sacc[t][3]));
            }
            m0 = fmaxf(m0, __shfl_xor_sync(0xffffffffu, m0, 1));
            m0 = fmaxf(m0, __shfl_xor_sync(0xffffffffu, m0, 2));
            m1 = fmaxf(m1, __shfl_xor_sync(0xffffffffu, m1, 1));
            m1 = fmaxf(m1, __shfl_xor_sync(0xffffffffu, m1, 2));
            if ((lane & 3) == 0) { pmax[wn * 64 + r0] = m0; pmax[wn * 64 + r1] = m1; }
            __syncthreads();

            float mn0 = fmaxf(fmaxf(pmax[r0], pmax[64 + r0]), mrow[r0]);
            float mn1 = fmaxf(fmaxf(pmax[r1], pmax[64 + r1]), mrow[r1]);
            float s0 = 0.0f, s1 = 0.0f;
            uint32_t pw0[4], pw1[4];
#pragma unroll
            for (int t = 0; t < 4; t++) {
                float p00 = __expf(sacc[t][0] - mn0);
                float p01 = __expf(sacc[t][1] - mn0);
                float p10 = __expf(sacc[t][2] - mn1);
                float p11 = __expf(sacc[t][3] - mn1);
                s0 += p00 + p01; s1 += p10 + p11;
                pw0[t] = pack_h2(__float2half_rn(p00), __float2half_rn(p01));
                pw1[t] = pack_h2(__float2half_rn(p10), __float2half_rn(p11));
            }
            s0 += __shfl_xor_sync(0xffffffffu, s0, 1);
            s0 += __shfl_xor_sync(0xffffffffu, s0, 2);
            s1 += __shfl_xor_sync(0xffffffffu, s1, 1);
            s1 += __shfl_xor_sync(0xffffffffu, s1, 2);
#pragma unroll
            for (int t = 0; t < 4; t++) {
                int gidx = wn * 4 + (t >> 1) * 2 + (t & 1);
                *reinterpret_cast<uint32_t*>(sm + AP + sw128(r0, gidx) + (lane & 3) * 4) = pw0[t];
                *reinterpret_cast<uint32_t*>(sm + AP + sw128(r1, gidx) + (lane & 3) * 4) = pw1[t];
            }
            if ((lane & 3) == 0) { psum[wn * 64 + r0] = s0; psum[wn * 64 + r1] = s1; }
            __syncthreads();

            if (tid < 64) {
                float mold = mrow[tid];
                float mnew = fmaxf(fmaxf(pmax[tid], pmax[64 + tid]), mold);
                float corr = __expf(mold - mnew);
                lrow[tid] = lrow[tid] * corr + psum[tid] + psum[64 + tid];
                mrow[tid] = mnew;
                crow[tid] = corr;
            }
        }

        if (j0 + 64 <= jhi) load_k(j0 + 64);
        CP_COMMIT();
        CP_WAIT1();
        __syncthreads();

        // ---- rescale O, then O += P V ----
        {
            float c0 = crow[r0];
            float c1 = crow[r1];
#pragma unroll
            for (int t = 0; t < 16; t++) {
                oacc[t][0] *= c0; oacc[t][1] *= c0;
                oacc[t][2] *= c1; oacc[t][3] *= c1;
            }
        }
        const int prow = wm * 16 + (lane & 15);
        const int vk   = lane & 15;
        const int vng  = lane >> 4;
#pragma unroll
        for (int ks = 0; ks < 4; ks++) {
            uint32_t a[4];
            ldsm_x4(a, sb + AP + sw128(prow, ks * 2 + kgl));
            int krow = ks * 16 + vk;
#pragma unroll
            for (int ng = 0; ng < 8; ng++) {
                uint32_t vv[4];
                int gv = wn * 16 + ng * 2 + vng;
                ldsm_x4_trans(vv, sb + AV + sw512(krow, gv));
#pragma unroll
                for (int sub = 0; sub < 2; sub++)
                    mma16816h(oacc[ng * 2 + sub], a, vv[2 * sub], vv[2 * sub + 1]);
            }
        }
        __syncthreads();

        if (j0 + 64 <= jhi) load_v(j0 + 64);
        CP_COMMIT();
    }

    const int r0 = wm * 16 + er;
    if (is_split) {
        // ---- write unnormalized partials ----
        const int p = ((qt - 32) * 8 + h) * 2 + half;
        float* Op = g_opart + (size_t)p * 64 * 256;
        if (tid < 64) {
            g_mpart[p * 64 + tid] = mrow[tid];
            g_lpart[p * 64 + tid] = lrow[tid];
        }
#pragma unroll
        for (int t = 0; t < 16; t++) {
            int col = wn * 128 + (t >> 1) * 16 + (t & 1) * 8 + ec;
            *reinterpret_cast<float2*>(&Op[r0 * 256 + col]) =
                make_float2(oacc[t][0], oacc[t][1]);
            *reinterpret_cast<float2*>(&Op[(r0 + 8) * 256 + col]) =
                make_float2(oacc[t][2], oacc[t][3]);
        }
    } else {
        // ---- direct epilogue: 1/l, sigmoid gate, write fp16 y ----
        const float li0 = 1.0f / lrow[r0];
        const float li1 = 1.0f / lrow[r0 + 8];
        const size_t base0 = (size_t)(i0 + r0) * ODIM + h * HDIM;
        const size_t base1 = (size_t)(i0 + r0 + 8) * ODIM + h * HDIM;
#pragma unroll
        for (int t = 0; t < 16; t++) {
            int col = wn * 128 + (t >> 1) * 16 + (t & 1) * 8 + ec;
            __half2 gh0 = *reinterpret_cast<const __half2*>(&g_gate16[base0 + col]);
            __half2 gh1 = *reinterpret_cast<const __half2*>(&g_gate16[base1 + col]);
            float2 gt0 = __half22float2(gh0);
            float2 gt1 = __half22float2(gh1);
            float v00 = oacc[t][0] * li0 * (1.0f / (1.0f + __expf(-gt0.x)));
            float v01 = oacc[t][1] * li0 * (1.0f / (1.0f + __expf(-gt0.y)));
            float v10 = oacc[t][2] * li1 * (1.0f / (1.0f + __expf(-gt1.x)));
            float v11 = oacc[t][3] * li1 * (1.0f / (1.0f + __expf(-gt1.y)));
            *reinterpret_cast<__half2*>(&g_y[base0 + col]) =
                __halves2half2(__float2half_rn(v00), __float2half_rn(v01));
            *reinterpret_cast<__half2*>(&g_y[base1 + col]) =
                __halves2half2(__float2half_rn(v10), __float2half_rn(v11));
        }
    }
}

// ---------------- split-KV merge: combine 2 halves, gate, write y ----------------
// grid (2048, 8), 256 threads: one block per (split-region row, head)
__global__ __launch_bounds__(256) void attn_merge_kernel()
{
    const int lr = blockIdx.x;           // 0..2047 (rows 2048..4095)
    const int h  = blockIdx.y;
    const int qt  = 32 + (lr >> 6);
    const int row = lr & 63;
    const int p0 = ((qt - 32) * 8 + h) * 2;

    const float m1 = g_mpart[p0 * 64 + row];
    const float l1 = g_lpart[p0 * 64 + row];
    const float m2 = g_mpart[(p0 + 1) * 64 + row];
    const float l2 = g_lpart[(p0 + 1) * 64 + row];
    const float m  = fmaxf(m1, m2);
    const float a1 = __expf(m1 - m);
    const float a2 = __expf(m2 - m);
    const float inv = 1.0f / (l1 * a1 + l2 * a2);

    const float* O1 = g_opart + ((size_t)p0 * 64 + row) * 256;
    const float* O2 = g_opart + ((size_t)(p0 + 1) * 64 + row) * 256;
    const int col = threadIdx.x;         // 0..255
    const size_t base = (size_t)(2048 + lr) * ODIM + h * HDIM;

    float o = (O1[col] * a1 + O2[col] * a2) * inv;
    float gt = __half2float(g_gate16[base + col]);
    g_y[base + col] = __float2half_rn(o * (1.0f / (1.0f + __expf(-gt))));
}

// ---------------- launch ----------------
extern "C" void kernel_launch(void* const* d_in, const int* in_sizes, int n_in,
                              void* d_out, int out_size)
{
    const float* x    = (const float*)d_in[0];
    const float* cosb = (const float*)d_in[1];
    const float* sinb = (const float*)d_in[2];
    const float* wq   = (const float*)d_in[4];
    const float* wk   = (const float*)d_in[5];
    const float* wv   = (const float*)d_in[6];
    const float* wo   = (const float*)d_in[7];
    const float* qg   = (const float*)d_in[8];
    const float* kg   = (const float*)d_in[9];
    float* out        = (float*)d_out;

    float *p_qraw, *p_kvraw;
    cudaGetSymbolAddress((void**)&p_qraw,  g_qraw);
    cudaGetSymbolAddress((void**)&p_kvraw, g_kvraw);

    __half *p_x16, *p_wq16, *p_wkv16, *p_wo16, *p_y;
    cudaGetSymbolAddress((void**)&p_x16,   g_x16);
    cudaGetSymbolAddress((void**)&p_wq16,  g_wq16);
    cudaGetSymbolAddress((void**)&p_wkv16, g_wkv16);
    cudaGetSymbolAddress((void**)&p_wo16,  g_wo16);
    cudaGetSymbolAddress((void**)&p_y,     g_y);

    cudaFuncSetAttribute(mma_gemmh, cudaFuncAttributeMaxDynamicSharedMemorySize, GEMM1_SMEM);
    cudaFuncSetAttribute(attn_mma_kernel, cudaFuncAttributeMaxDynamicSharedMemorySize, ATT_SMEM);

    // 0) operand prep (all fp16, 1-term)
    cast_h_kernel<<<2048, 256>>>(x, p_x16, (size_t)L_SEQ * IDIM / 4);
    transpose_h_kernel<<<dim3((ODIM*2)/32, IDIM/32), 256>>>(wq, p_wq16, IDIM, ODIM*2);
    transpose_h_kernel<<<dim3(NKV/32, IDIM/32), 256>>>(wk, p_wkv16, IDIM, NKV);
    transpose_h_kernel<<<dim3(NKV/32, IDIM/32), 256>>>(
        wv, p_wkv16 + (size_t)512 * IDIM, IDIM, NKV);
    transpose_h_kernel<<<dim3(IDIM/32, ODIM/32), 256>>>(wo, p_wo16, ODIM, IDIM);

    // 1) projections: Q (N=4096) and fused KV (N=1024), 1-term fp16
    mma_gemmh<<<dim3((ODIM*2)/128, L_SEQ/128), 256, GEMM1_SMEM>>>(p_x16, p_wq16, p_qraw, ODIM*2);
    mma_gemmh<<<dim3(1024/128,     L_SEQ/128), 256, GEMM1_SMEM>>>(p_x16, p_wkv16, p_kvraw, 1024);

    // 2) warp-per-row norms + RoPE -> single fp16
    qnorm_rope_kernel<<<L_SEQ * NHEADS / 8,  256>>>(cosb, sinb, qg);
    knorm_rope_v_kernel<<<L_SEQ * NGROUPS / 8, 256>>>(cosb, sinb, kg);

    // 3) split-KV MMA flash attention + merge
    attn_mma_kernel<<<dim3(96, NHEADS), 256, ATT_SMEM>>>();
    attn_merge_kernel<<<dim3(2048, NHEADS), 256>>>();

    // 4) output projection: 1-term fp16
    mma_gemmh<<<dim3(IDIM/128, L_SEQ/128), 256, GEMM1_SMEM>>>(p_y, p_wo16, out, IDIM);
}

// round 16
// speedup vs baseline: 1.6000x; 1.0274x over previous
#include <cuda_runtime.h>
#include <cuda_bf16.h>
#include <cuda_fp16.h>
#include <math.h>
#include <stdint.h>

// ---------------- problem constants ----------------
#define L_SEQ   4096
#define IDIM    2048
#define NHEADS  8
#define NGROUPS 2
#define HDIM    256
#define ROPED   64
#define ODIM    (NHEADS*HDIM)     // 2048
#define NKV     (NGROUPS*HDIM)    // 512
#define QSCALE  0.0625f           // 256^-0.5
#define SMAX    8.0f              // fixed softmax max shift (|S| <= 16 by Cauchy-Schwarz)

// ---------------- warp-MMA helpers (standard PTX, sm_80+) ----------------
__device__ __forceinline__ void ldsm_x4(uint32_t* r, uint32_t addr) {
    asm volatile("ldmatrix.sync.aligned.m8n8.x4.shared.b16 {%0,%1,%2,%3}, [%4];"
        : "=r"(r[0]), "=r"(r[1]), "=r"(r[2]), "=r"(r[3]) : "r"(addr));
}
__device__ __forceinline__ void ldsm_x4_trans(uint32_t* r, uint32_t addr) {
    asm volatile("ldmatrix.sync.aligned.m8n8.x4.trans.shared.b16 {%0,%1,%2,%3}, [%4];"
        : "=r"(r[0]), "=r"(r[1]), "=r"(r[2]), "=r"(r[3]) : "r"(addr));
}
__device__ __forceinline__ void mma16816h(float* d, const uint32_t* a, uint32_t b0, uint32_t b1) {
    asm volatile("mma.sync.aligned.m16n8k16.row.col.f32.f16.f16.f32 "
        "{%0,%1,%2,%3}, {%4,%5,%6,%7}, {%8,%9}, {%0,%1,%2,%3};"
        : "+f"(d[0]), "+f"(d[1]), "+f"(d[2]), "+f"(d[3])
        : "r"(a[0]), "r"(a[1]), "r"(a[2]), "r"(a[3]), "r"(b0), "r"(b1));
}
__device__ __forceinline__ void cp_async16(uint32_t dst, const void* src) {
    asm volatile("cp.async.cg.shared.global [%0], [%1], 16;" :: "r"(dst), "l"(src));
}
#define CP_COMMIT() asm volatile("cp.async.commit_group;" ::: "memory")
#define CP_WAIT1()  asm volatile("cp.async.wait_group 1;" ::: "memory")
#define CP_WAIT0()  asm volatile("cp.async.wait_group 0;" ::: "memory")

__device__ __forceinline__ uint32_t smem_to_u32(const void* p) {
    uint32_t a;
    asm("{ .reg .u64 t; cvta.to.shared.u64 t, %1; cvt.u32.u64 %0, t; }" : "=r"(a) : "l"(p));
    return a;
}
__device__ __forceinline__ uint32_t pack_h2(__half a, __half b) {
    __half2 t = __halves2half2(a, b);
    return *reinterpret_cast<uint32_t*>(&t);
}

// ---------------- scratch (device globals) ----------------
__device__ float  g_qraw [(size_t)L_SEQ * (ODIM*2)];
__device__ __half g_gate16[(size_t)L_SEQ * ODIM];
__device__ float  g_kvraw[(size_t)L_SEQ * 1024];    // cols 0-511 = K, 512-1023 = V

// fp16 operands (all GEMMs 1-term fp16)
__device__ __half g_x16  [(size_t)L_SEQ * IDIM];
__device__ __half g_wq16 [(size_t)(ODIM*2) * IDIM];
__device__ __half g_wkv16[(size_t)1024 * IDIM];     // rows 0-511 wk^T, 512-1023 wv^T
__device__ __half g_wo16 [(size_t)IDIM * ODIM];
__device__ __half g_y    [(size_t)L_SEQ * ODIM];
// attention operands (single fp16)
__device__ __half g_q16 [(size_t)L_SEQ * ODIM];     // pre-scaled
__device__ __half g_k16 [(size_t)L_SEQ * NKV];
__device__ __half g_v16 [(size_t)L_SEQ * NKV];
// split-KV partials (fixed-max: no m needed): 512 pieces, 64 rows x 256 cols
__device__ float g_opart[(size_t)512 * 64 * 256];
__device__ float g_lpart[(size_t)512 * 64];

// ---------------- cast kernel: fp32 -> fp16 ----------------
__global__ __launch_bounds__(256) void cast_h_kernel(
    const float* __restrict__ in, __half* __restrict__ out, size_t n4)
{
    size_t i = (size_t)blockIdx.x * blockDim.x + threadIdx.x;
    size_t stride = (size_t)gridDim.x * blockDim.x;
    for (; i < n4; i += stride) {
        float4 v = reinterpret_cast<const float4*>(in)[i];
        __half2 a = __halves2half2(__float2half_rn(v.x), __float2half_rn(v.y));
        __half2 b = __halves2half2(__float2half_rn(v.z), __float2half_rn(v.w));
        reinterpret_cast<__half2*>(out)[i*2]   = a;
        reinterpret_cast<__half2*>(out)[i*2+1] = b;
    }
}

// ---------------- transpose: W[K][N] fp32 -> Wt [N][K] fp16 ----------------
__global__ __launch_bounds__(256) void transpose_h_kernel(
    const float* __restrict__ W, __half* __restrict__ T, int Kdim, int Ndim)
{
    __shared__ float tile[32][33];
    int n0 = blockIdx.x * 32;
    int k0 = blockIdx.y * 32;
    int tx = threadIdx.x & 31;
    int ty = threadIdx.x >> 5;
#pragma unroll
    for (int r = 0; r < 4; r++)
        tile[ty + 8*r][tx] = W[(size_t)(k0 + ty + 8*r) * Ndim + n0 + tx];
    __syncthreads();
#pragma unroll
    for (int r = 0; r < 4; r++) {
        float v = tile[tx][ty + 8*r];
        T[(size_t)(n0 + ty + 8*r) * Kdim + k0 + tx] = __float2half_rn(v);
    }
}

// ---------------- 1-term fp16 GEMM: C = A(fp16) @ B(fp16)^T ----------------
#define GBK 32
#define NCHUNK (IDIM / GBK)            // 64
#define RS 80                          // smem row stride bytes
#define MAT_BYTES (128 * RS)           // 10240
#define MAT2_STAGE (2 * MAT_BYTES)     // 20480
#define GEMM1_SMEM (2 * MAT2_STAGE)    // 40960

__global__ __launch_bounds__(256) void mma_gemmh(
    const __half* __restrict__ A, const __half* __restrict__ B,
    float* __restrict__ C, int N)
{
    extern __shared__ char smem[];
    const uint32_t sb = smem_to_u32(smem);

    const int tid  = threadIdx.x;
    const int lane = tid & 31;
    const int wid  = tid >> 5;
    const int wm   = wid & 1;
    const int wn   = wid >> 1;
    const int m0   = blockIdx.y * 128;
    const int n0   = blockIdx.x * 128;

    auto issue_loads = [&](int chunk) {
        const int stage = chunk & 1;
        const uint32_t s0 = sb + stage * MAT2_STAGE;
#pragma unroll
        for (int j = 0; j < 4; j++) {
            int idx = tid + 256 * j;          // 0..1023
            int mat = idx >> 9;               // 0=A,1=B
            int wi  = idx & 511;
            int row = wi >> 2;
            int c   = wi & 3;
            const __half* gp = (mat == 0) ? A + (size_t)(m0 + row) * IDIM
                                          : B + (size_t)(n0 + row) * IDIM;
            cp_async16(s0 + mat * MAT_BYTES + row * RS + c * 16,
                       gp + chunk * GBK + c * 8);
        }
    };

    float acc[4][4][4];
#pragma unroll
    for (int mi = 0; mi < 4; mi++)
#pragma unroll
        for (int ni = 0; ni < 4; ni++)
#pragma unroll
            for (int r = 0; r < 4; r++) acc[mi][ni][r] = 0.0f;

    const uint32_t a_row = wm * 64 + (lane & 15);
    const uint32_t b_row = wn * 32 + (lane & 15);
    const uint32_t colb  = (lane >> 4) * 16;

    issue_loads(0); CP_COMMIT();

    for (int i = 0; i < NCHUNK; i++) {
        const int stage = i & 1;
        if (i + 1 < NCHUNK) { issue_loads(i + 1); CP_COMMIT(); CP_WAIT1(); }
        else                { CP_WAIT0(); }
        __syncthreads();

        const uint32_t sA = sb + stage * MAT2_STAGE;
        const uint32_t sB = sA + MAT_BYTES;

#pragma unroll
        for (int ks = 0; ks < 2; ks++) {
            const uint32_t kb = ks * 32 + colb;
            uint32_t a[4][4], b[2][4];
#pragma unroll
            for (int mi = 0; mi < 4; mi++)
                ldsm_x4(a[mi], sA + (a_row + mi * 16) * RS + kb);
#pragma unroll
            for (int nt = 0; nt < 2; nt++)
                ldsm_x4(b[nt], sB + (b_row + nt * 16) * RS + kb);
#pragma unroll
            for (int mi = 0; mi < 4; mi++) {
#pragma unroll
                for (int ni = 0; ni < 4; ni++) {
                    const int nt = ni >> 1, sub = ni & 1;
                    mma16816h(acc[mi][ni], a[mi], b[nt][sub], b[nt][2 + sub]);
                }
            }
        }
        __syncthreads();
    }

    const int er = lane >> 2;
    const int ec = (lane & 3) * 2;
#pragma unroll
    for (int mi = 0; mi < 4; mi++) {
#pragma unroll
        for (int ni = 0; ni < 4; ni++) {
            int row = m0 + wm * 64 + mi * 16 + er;
            int col = n0 + wn * 32 + ni * 8 + ec;
            *reinterpret_cast<float2*>(&C[(size_t)row * N + col]) =
                make_float2(acc[mi][ni][0], acc[mi][ni][1]);
            *reinterpret_cast<float2*>(&C[(size_t)(row + 8) * N + col]) =
                make_float2(acc[mi][ni][2], acc[mi][ni][3]);
        }
    }
}

// ---------------- warp-per-row RMSNorm + RoPE for Q (+ gate fp16) ----------------
__global__ __launch_bounds__(256) void qnorm_rope_kernel(
    const float* __restrict__ cosb, const float* __restrict__ sinb,
    const float* __restrict__ gamma)
{
    const int ridx = blockIdx.x * 8 + (threadIdx.x >> 5);  // 0..32767
    const int lane = threadIdx.x & 31;
    const int l = ridx >> 3, h = ridx & 7;
    const float* row = g_qraw + (size_t)l * (ODIM * 2) + h * 512;

    float4 a = *reinterpret_cast<const float4*>(row + lane * 8);
    float4 b = *reinterpret_cast<const float4*>(row + lane * 8 + 4);
    float y[8] = {a.x, a.y, a.z, a.w, b.x, b.y, b.z, b.w};

    float s = 0.0f;
#pragma unroll
    for (int j = 0; j < 8; j++) s += y[j] * y[j];
#pragma unroll
    for (int o = 16; o > 0; o >>= 1) s += __shfl_xor_sync(0xffffffffu, s, o);
    float rstd = rsqrtf(s * (1.0f / 256.0f) + 1e-6f);

    float4 ga = *reinterpret_cast<const float4*>(gamma + lane * 8);
    float4 gb = *reinterpret_cast<const float4*>(gamma + lane * 8 + 4);
    float gm[8] = {ga.x, ga.y, ga.z, ga.w, gb.x, gb.y, gb.z, gb.w};
#pragma unroll
    for (int j = 0; j < 8; j++) y[j] *= rstd * gm[j];

    float oth[8];
#pragma unroll
    for (int j = 0; j < 8; j++) oth[j] = __shfl_xor_sync(0xffffffffu, y[j], 4);
    if (lane < 8) {
        const float* cb  = cosb + (size_t)l * ROPED + lane * 8;
        const float* sbp = sinb + (size_t)l * ROPED + lane * 8;
#pragma unroll
        for (int j = 0; j < 8; j++) {
            float rot = (lane < 4) ? -oth[j] : oth[j];
            y[j] = y[j] * cb[j] + rot * sbp[j];
        }
    }

    float4 g0 = *reinterpret_cast<const float4*>(row + 256 + lane * 8);
    float4 g1 = *reinterpret_cast<const float4*>(row + 256 + lane * 8 + 4);
    float gv[8] = {g0.x, g0.y, g0.z, g0.w, g1.x, g1.y, g1.z, g1.w};

    size_t o = (size_t)l * ODIM + h * HDIM + lane * 8;
    uint32_t qw[4], gw[4];
#pragma unroll
    for (int j = 0; j < 4; j++) {
        qw[j] = pack_h2(__float2half_rn(y[j*2] * QSCALE), __float2half_rn(y[j*2+1] * QSCALE));
        gw[j] = pack_h2(__float2half_rn(gv[j*2]), __float2half_rn(gv[j*2+1]));
    }
    *reinterpret_cast<uint4*>(&g_q16[o])    = make_uint4(qw[0], qw[1], qw[2], qw[3]);
    *reinterpret_cast<uint4*>(&g_gate16[o]) = make_uint4(gw[0], gw[1], gw[2], gw[3]);
}

// ---------------- warp-per-row RMSNorm + RoPE for K + V cast ----------------
__global__ __launch_bounds__(256) void knorm_rope_v_kernel(
    const float* __restrict__ cosb, const float* __restrict__ sinb,
    const float* __restrict__ gamma)
{
    const int ridx = blockIdx.x * 8 + (threadIdx.x >> 5);  // 0..8191
    const int lane = threadIdx.x & 31;
    const int l = ridx >> 1, g = ridx & 1;
    const float* krow = g_kvraw + (size_t)l * 1024 + g * HDIM;
    const float* vrow = g_kvraw + (size_t)l * 1024 + 512 + g * HDIM;

    float4 a = *reinterpret_cast<const float4*>(krow + lane * 8);
    float4 b = *reinterpret_cast<const float4*>(krow + lane * 8 + 4);
    float y[8] = {a.x, a.y, a.z, a.w, b.x, b.y, b.z, b.w};

    float s = 0.0f;
#pragma unroll
    for (int j = 0; j < 8; j++) s += y[j] * y[j];
#pragma unroll
    for (int o = 16; o > 0; o >>= 1) s += __shfl_xor_sync(0xffffffffu, s, o);
    float rstd = rsqrtf(s * (1.0f / 256.0f) + 1e-6f);

    float4 ga = *reinterpret_cast<const float4*>(gamma + lane * 8);
    float4 gb = *reinterpret_cast<const float4*>(gamma + lane * 8 + 4);
    float gm[8] = {ga.x, ga.y, ga.z, ga.w, gb.x, gb.y, gb.z, gb.w};
#pragma unroll
    for (int j = 0; j < 8; j++) y[j] *= rstd * gm[j];

    float oth[8];
#pragma unroll
    for (int j = 0; j < 8; j++) oth[j] = __shfl_xor_sync(0xffffffffu, y[j], 4);
    if (lane < 8) {
        const float* cb  = cosb + (size_t)l * ROPED + lane * 8;
        const float* sbp = sinb + (size_t)l * ROPED + lane * 8;
#pragma unroll
        for (int j = 0; j < 8; j++) {
            float rot = (lane < 4) ? -oth[j] : oth[j];
            y[j] = y[j] * cb[j] + rot * sbp[j];
        }
    }

    float4 v0 = *reinterpret_cast<const float4*>(vrow + lane * 8);
    float4 v1 = *reinterpret_cast<const float4*>(vrow + lane * 8 + 4);
    float vv[8] = {v0.x, v0.y, v0.z, v0.w, v1.x, v1.y, v1.z, v1.w};

    size_t o = (size_t)l * NKV + g * HDIM + lane * 8;
    uint32_t kw[4], vw[4];
#pragma unroll
    for (int j = 0; j < 4; j++) {
        kw[j] = pack_h2(__float2half_rn(y[j*2]), __float2half_rn(y[j*2+1]));
        vw[j] = pack_h2(__float2half_rn(vv[j*2]), __float2half_rn(vv[j*2+1]));
    }
    *reinterpret_cast<uint4*>(&g_k16[o]) = make_uint4(kw[0], kw[1], kw[2], kw[3]);
    *reinterpret_cast<uint4*>(&g_v16[o]) = make_uint4(vw[0], vw[1], vw[2], vw[3]);
}

// ---------------- MMA flash attention, fixed-max softmax, split-KV ----------------
#define AQ   0
#define AK   32768
#define AV   65536
#define AP   98304                  // 64 x 128B (fp16 P, swizzled)
#define APS  (AP + 8192)            // l partials: 2 x 64 floats
#define ATT_SMEM (APS + 512)        // 107008

__device__ __forceinline__ uint32_t sw512(int row, int g) {
    return (uint32_t)(row * 512 + ((g ^ (row & 7)) << 4));
}
__device__ __forceinline__ uint32_t sw128(int row, int g) {
    return (uint32_t)(row * 128 + ((g ^ (row & 7)) << 4));
}

// grid (96, 8): bx 0..63 = split pieces (qt = 63 - bx/2, half = bx&1);
//               bx 64..95 = full blocks (qt = 95 - bx, i.e. 31..0)
__global__ __launch_bounds__(256, 2) void attn_mma_kernel()
{
    extern __shared__ char sm[];
    const uint32_t sb = smem_to_u32(sm);
    const int tid  = threadIdx.x;
    const int lane = tid & 31;
    const int wid  = tid >> 5;
    const int bx   = blockIdx.x;
    const int h    = blockIdx.y;
    const int g    = h >> 2;

    int qt, jt0, jt1, half;
    bool is_split;
    if (bx < 64) {
        is_split = true;
        half = bx & 1;
        qt = 63 - (bx >> 1);
        int nt = qt + 1;
        int sp = nt >> 1;
        jt0 = half ? sp : 0;
        jt1 = half ? nt : sp;
    } else {
        is_split = false;
        half = 0;
        qt = 95 - bx;
        jt0 = 0;
        jt1 = qt + 1;
    }
    const int i0  = qt * 64;
    const int jlo = jt0 * 64;
    const int jhi = (jt1 - 1) * 64;      // last tile start

    float* psum = reinterpret_cast<float*>(sm + APS);

    auto load_k = [&](int j0) {
        const size_t rbase = ((size_t)j0 * NGROUPS + g) * HDIM;
        const size_t rstr  = (size_t)NGROUPS * HDIM;
#pragma unroll
        for (int i = 0; i < 8; i++) {
            int idx = tid + 256 * i;
            int row = idx >> 5, gr = idx & 31;
            cp_async16(sb + AK + sw512(row, gr),
                       (const char*)g_k16 + (rbase + (size_t)row * rstr) * 2 + gr * 16);
        }
    };
    auto load_v = [&](int j0) {
        const size_t rbase = ((size_t)j0 * NGROUPS + g) * HDIM;
        const size_t rstr  = (size_t)NGROUPS * HDIM;
#pragma unroll
        for (int i = 0; i < 8; i++) {
            int idx = tid + 256 * i;
            int row = idx >> 5, gr = idx & 31;
            cp_async16(sb + AV + sw512(row, gr),
                       (const char*)g_v16 + (rbase + (size_t)row * rstr) * 2 + gr * 16);
        }
    };

    // ---- prolog: Q, K(jlo), V(jlo) ----
    {
        const char* q16 = (const char*)(g_q16 + ((size_t)i0 * NHEADS + h) * HDIM);
        const size_t rstr = (size_t)NHEADS * HDIM * 2;
#pragma unroll
        for (int i = 0; i < 8; i++) {
            int idx = tid + 256 * i;
            int row = idx >> 5, gr = idx & 31;
            cp_async16(sb + AQ + sw512(row, gr), q16 + (size_t)row * rstr + gr * 16);
        }
    }
    CP_COMMIT();
    load_k(jlo); CP_COMMIT();
    load_v(jlo); CP_COMMIT();

    const int wm = wid & 3;
    const int wn = wid >> 2;
    const int er = lane >> 2;
    const int ec = (lane & 3) * 2;
    const int kgl = lane >> 4;
    const int r0 = wm * 16 + er;
    const int r1 = r0 + 8;

    float oacc[16][4];
#pragma unroll
    for (int t = 0; t < 16; t++)
#pragma unroll
        for (int r = 0; r < 4; r++) oacc[t][r] = 0.0f;
    float lac0 = 0.0f, lac1 = 0.0f;     // register l accumulators (rows r0, r1)

    for (int j0 = jlo; j0 <= jhi; j0 += 64) {
        CP_WAIT1();
        __syncthreads();

        // ---- S = Q K^T ----
        float sacc[4][4];
#pragma unroll
        for (int t = 0; t < 4; t++)
#pragma unroll
            for (int r = 0; r < 4; r++) sacc[t][r] = 0.0f;

        const int arow  = wm * 16 + (lane & 15);
        const int brow0 = wn * 32 + (lane & 15);
#pragma unroll 4
        for (int ks = 0; ks < 16; ks++) {
            int kg = ks * 2 + kgl;
            uint32_t a[4], b[2][4];
            ldsm_x4(a, sb + AQ + sw512(arow, kg));
            ldsm_x4(b[0], sb + AK + sw512(brow0, kg));
            ldsm_x4(b[1], sb + AK + sw512(brow0 + 16, kg));
#pragma unroll
            for (int nt = 0; nt < 2; nt++)
#pragma unroll
                for (int sub = 0; sub < 2; sub++)
                    mma16816h(sacc[nt * 2 + sub], a, b[nt][sub], b[nt][2 + sub]);
        }

        // ---- fixed-max softmax: p = exp(S - 8), no cross-warp exchange ----
        {
            const int lim0 = i0 + r0 - j0;
            const int lim1 = lim0 + 8;
            uint32_t pw0[4], pw1[4];
#pragma unroll
            for (int t = 0; t < 4; t++) {
                int col = wn * 32 + (t >> 1) * 16 + (t & 1) * 8 + ec;
                if (col > lim0)     sacc[t][0] = -INFINITY;
                if (col + 1 > lim0) sacc[t][1] = -INFINITY;
                if (col > lim1)     sacc[t][2] = -INFINITY;
                if (col + 1 > lim1) sacc[t][3] = -INFINITY;
                float p00 = __expf(sacc[t][0] - SMAX);
                float p01 = __expf(sacc[t][1] - SMAX);
                float p10 = __expf(sacc[t][2] - SMAX);
                float p11 = __expf(sacc[t][3] - SMAX);
                lac0 += p00 + p01; lac1 += p10 + p11;
                pw0[t] = pack_h2(__float2half_rn(p00), __float2half_rn(p01));
                pw1[t] = pack_h2(__float2half_rn(p10), __float2half_rn(p11));
            }
#pragma unroll
            for (int t = 0; t < 4; t++) {
                int gidx = wn * 4 + (t >> 1) * 2 + (t & 1);
                *reinterpret_cast<uint32_t*>(sm + AP + sw128(r0, gidx) + (lane & 3) * 4) = pw0[t];
                *reinterpret_cast<uint32_t*>(sm + AP + sw128(r1, gidx) + (lane & 3) * 4) = pw1[t];
            }
        }
        __syncthreads();          // P visible; K buffer dead

        if (j0 + 64 <= jhi) load_k(j0 + 64);
        CP_COMMIT();
        CP_WAIT1();               // V(j0) ready
        __syncthreads();

        // ---- O += P V (no rescale needed) ----
        const int prow = wm * 16 + (lane & 15);
        const int vk   = lane & 15;
        const int vng  = lane >> 4;
#pragma unroll
        for (int ks = 0; ks < 4; ks++) {
            uint32_t a[4];
            ldsm_x4(a, sb + AP + sw128(prow, ks * 2 + kgl));
            int krow = ks * 16 + vk;
#pragma unroll
            for (int ng = 0; ng < 8; ng++) {
                uint32_t vv[4];
                int gv = wn * 16 + ng * 2 + vng;
                ldsm_x4_trans(vv, sb + AV + sw512(krow, gv));
#pragma unroll
                for (int sub = 0; sub < 2; sub++)
                    mma16816h(oacc[ng * 2 + sub], a, vv[2 * sub], vv[2 * sub + 1]);
            }
        }
        __syncthreads();          // V buffer dead

        if (j0 + 64 <= jhi) load_v(j0 + 64);
        CP_COMMIT();
    }

    // ---- final l reduction (once) ----
    lac0 += __shfl_xor_sync(0xffffffffu, lac0, 1);
    lac0 += __shfl_xor_sync(0xffffffffu, lac0, 2);
    lac1 += __shfl_xor_sync(0xffffffffu, lac1, 1);
    lac1 += __shfl_xor_sync(0xffffffffu, lac1, 2);
    if ((lane & 3) == 0) { psum[wn * 64 + r0] = lac0; psum[wn * 64 + r1] = lac1; }
    __syncthreads();

    if (is_split) {
        // ---- write unnormalized partials (common fixed scale, no m) ----
        const int p = ((qt - 32) * 8 + h) * 2 + half;
        float* Op = g_opart + (size_t)p * 64 * 256;
        if (tid < 64) g_lpart[p * 64 + tid] = psum[tid] + psum[64 + tid];
#pragma unroll
        for (int t = 0; t < 16; t++) {
            int col = wn * 128 + (t >> 1) * 16 + (t & 1) * 8 + ec;
            *reinterpret_cast<float2*>(&Op[r0 * 256 + col]) =
                make_float2(oacc[t][0], oacc[t][1]);
            *reinterpret_cast<float2*>(&Op[(r0 + 8) * 256 + col]) =
                make_float2(oacc[t][2], oacc[t][3]);
        }
    } else {
        // ---- direct epilogue: 1/l, sigmoid gate, write fp16 y ----
        const float li0 = 1.0f / (psum[r0] + psum[64 + r0]);
        const float li1 = 1.0f / (psum[r1] + psum[64 + r1]);
        const size_t base0 = (size_t)(i0 + r0) * ODIM + h * HDIM;
        const size_t base1 = (size_t)(i0 + r1) * ODIM + h * HDIM;
#pragma unroll
        for (int t = 0; t < 16; t++) {
            int col = wn * 128 + (t >> 1) * 16 + (t & 1) * 8 + ec;
            __half2 gh0 = *reinterpret_cast<const __half2*>(&g_gate16[base0 + col]);
            __half2 gh1 = *reinterpret_cast<const __half2*>(&g_gate16[base1 + col]);
            float2 gt0 = __half22float2(gh0);
            float2 gt1 = __half22float2(gh1);
            float v00 = oacc[t][0] * li0 * (1.0f / (1.0f + __expf(-gt0.x)));
            float v01 = oacc[t][1] * li0 * (1.0f / (1.0f + __expf(-gt0.y)));
            float v10 = oacc[t][2] * li1 * (1.0f / (1.0f + __expf(-gt1.x)));
            float v11 = oacc[t][3] * li1 * (1.0f / (1.0f + __expf(-gt1.y)));
            *reinterpret_cast<__half2*>(&g_y[base0 + col]) =
                __halves2half2(__float2half_rn(v00), __float2half_rn(v01));
            *reinterpret_cast<__half2*>(&g_y[base1 + col]) =
                __halves2half2(__float2half_rn(v10), __float2half_rn(v11));
        }
    }
}

// ---------------- split-KV merge (fixed-max): O = (O1+O2)/(l1+l2), gate ----------------
__global__ __launch_bounds__(256) void attn_merge_kernel()
{
    const int lr = blockIdx.x;           // 0..2047 (rows 2048..4095)
    const int h  = blockIdx.y;
    const int qt  = 32 + (lr >> 6);
    const int row = lr & 63;
    const int p0 = ((qt - 32) * 8 + h) * 2;

    const float l1 = g_lpart[p0 * 64 + row];
    const float l2 = g_lpart[(p0 + 1) * 64 + row];
    const float inv = 1.0f / (l1 + l2);

    const float* O1 = g_opart + ((size_t)p0 * 64 + row) * 256;
    const float* O2 = g_opart + ((size_t)(p0 + 1) * 64 + row) * 256;
    const int col = threadIdx.x;         // 0..255
    const size_t base = (size_t)(2048 + lr) * ODIM + h * HDIM;

    float o = (O1[col] + O2[col]) * inv;
    float gt = __half2float(g_gate16[base + col]);
    g_y[base + col] = __float2half_rn(o * (1.0f / (1.0f + __expf(-gt))));
}

// ---------------- launch ----------------
extern "C" void kernel_launch(void* const* d_in, const int* in_sizes, int n_in,
                              void* d_out, int out_size)
{
    const float* x    = (const float*)d_in[0];
    const float* cosb = (const float*)d_in[1];
    const float* sinb = (const float*)d_in[2];
    const float* wq   = (const float*)d_in[4];
    const float* wk   = (const float*)d_in[5];
    const float* wv   = (const float*)d_in[6];
    const float* wo   = (const float*)d_in[7];
    const float* qg   = (const float*)d_in[8];
    const float* kg   = (const float*)d_in[9];
    float* out        = (float*)d_out;

    float *p_qraw, *p_kvraw;
    cudaGetSymbolAddress((void**)&p_qraw,  g_qraw);
    cudaGetSymbolAddress((void**)&p_kvraw, g_kvraw);

    __half *p_x16, *p_wq16, *p_wkv16, *p_wo16, *p_y;
    cudaGetSymbolAddress((void**)&p_x16,   g_x16);
    cudaGetSymbolAddress((void**)&p_wq16,  g_wq16);
    cudaGetSymbolAddress((void**)&p_wkv16, g_wkv16);
    cudaGetSymbolAddress((void**)&p_wo16,  g_wo16);
    cudaGetSymbolAddress((void**)&p_y,     g_y);

    cudaFuncSetAttribute(mma_gemmh, cudaFuncAttributeMaxDynamicSharedMemorySize, GEMM1_SMEM);
    cudaFuncSetAttribute(attn_mma_kernel, cudaFuncAttributeMaxDynamicSharedMemorySize, ATT_SMEM);

    // 0) operand prep (all fp16, 1-term)
    cast_h_kernel<<<2048, 256>>>(x, p_x16, (size_t)L_SEQ * IDIM / 4);
    transpose_h_kernel<<<dim3((ODIM*2)/32, IDIM/32), 256>>>(wq, p_wq16, IDIM, ODIM*2);
    transpose_h_kernel<<<dim3(NKV/32, IDIM/32), 256>>>(wk, p_wkv16, IDIM, NKV);
    transpose_h_kernel<<<dim3(NKV/32, IDIM/32), 256>>>(
        wv, p_wkv16 + (size_t)512 * IDIM, IDIM, NKV);
    transpose_h_kernel<<<dim3(IDIM/32, ODIM/32), 256>>>(wo, p_wo16, ODIM, IDIM);

    // 1) projections: Q (N=4096) and fused KV (N=1024), 1-term fp16
    mma_gemmh<<<dim3((ODIM*2)/128, L_SEQ/128), 256, GEMM1_SMEM>>>(p_x16, p_wq16, p_qraw, ODIM*2);
    mma_gemmh<<<dim3(1024/128,     L_SEQ/128), 256, GEMM1_SMEM>>>(p_x16, p_wkv16, p_kvraw, 1024);

    // 2) warp-per-row norms + RoPE -> single fp16
    qnorm_rope_kernel<<<L_SEQ * NHEADS / 8,  256>>>(cosb, sinb, qg);
    knorm_rope_v_kernel<<<L_SEQ * NGROUPS / 8, 256>>>(cosb, sinb, kg);

    // 3) split-KV MMA flash attention (fixed-max softmax) + merge
    attn_mma_kernel<<<dim3(96, NHEADS), 256, ATT_SMEM>>>();
    attn_merge_kernel<<<dim3(2048, NHEADS), 256>>>();

    // 4) output projection: 1-term fp16
    mma_gemmh<<<dim3(IDIM/128, L_SEQ/128), 256, GEMM1_SMEM>>>(p_y, p_wo16, out, IDIM);
}

// round 17
// speedup vs baseline: 1.6214x; 1.0134x over previous
#include <cuda_runtime.h>
#include <cuda_bf16.h>
#include <cuda_fp16.h>
#include <math.h>
#include <stdint.h>

// ---------------- problem constants ----------------
#define L_SEQ   4096
#define IDIM    2048
#define NHEADS  8
#define NGROUPS 2
#define HDIM    256
#define ROPED   64
#define ODIM    (NHEADS*HDIM)     // 2048
#define NKV     (NGROUPS*HDIM)    // 512
#define QSCALE  0.0625f           // 256^-0.5
#define SMAX    8.0f              // fixed softmax shift (|S| <= 16 by Cauchy-Schwarz)

// ---------------- warp-MMA helpers (standard PTX, sm_80+) ----------------
__device__ __forceinline__ void ldsm_x4(uint32_t* r, uint32_t addr) {
    asm volatile("ldmatrix.sync.aligned.m8n8.x4.shared.b16 {%0,%1,%2,%3}, [%4];"
        : "=r"(r[0]), "=r"(r[1]), "=r"(r[2]), "=r"(r[3]) : "r"(addr));
}
__device__ __forceinline__ void ldsm_x4_trans(uint32_t* r, uint32_t addr) {
    asm volatile("ldmatrix.sync.aligned.m8n8.x4.trans.shared.b16 {%0,%1,%2,%3}, [%4];"
        : "=r"(r[0]), "=r"(r[1]), "=r"(r[2]), "=r"(r[3]) : "r"(addr));
}
__device__ __forceinline__ void mma16816h(float* d, const uint32_t* a, uint32_t b0, uint32_t b1) {
    asm volatile("mma.sync.aligned.m16n8k16.row.col.f32.f16.f16.f32 "
        "{%0,%1,%2,%3}, {%4,%5,%6,%7}, {%8,%9}, {%0,%1,%2,%3};"
        : "+f"(d[0]), "+f"(d[1]), "+f"(d[2]), "+f"(d[3])
        : "r"(a[0]), "r"(a[1]), "r"(a[2]), "r"(a[3]), "r"(b0), "r"(b1));
}
__device__ __forceinline__ void cp_async16(uint32_t dst, const void* src) {
    asm volatile("cp.async.cg.shared.global [%0], [%1], 16;" :: "r"(dst), "l"(src));
}
#define CP_COMMIT() asm volatile("cp.async.commit_group;" ::: "memory")
#define CP_WAIT1()  asm volatile("cp.async.wait_group 1;" ::: "memory")
#define CP_WAIT0()  asm volatile("cp.async.wait_group 0;" ::: "memory")

__device__ __forceinline__ uint32_t smem_to_u32(const void* p) {
    uint32_t a;
    asm("{ .reg .u64 t; cvta.to.shared.u64 t, %1; cvt.u32.u64 %0, t; }" : "=r"(a) : "l"(p));
    return a;
}
__device__ __forceinline__ uint32_t pack_h2(__half a, __half b) {
    __half2 t = __halves2half2(a, b);
    return *reinterpret_cast<uint32_t*>(&t);
}

// ---------------- scratch (device globals) ----------------
__device__ float  g_qraw [(size_t)L_SEQ * (ODIM*2)];
__device__ __half g_gate16[(size_t)L_SEQ * ODIM];
__device__ float  g_kvraw[(size_t)L_SEQ * 1024];    // cols 0-511 = K, 512-1023 = V

// fp16 operands (all GEMMs 1-term fp16)
__device__ __half g_x16  [(size_t)L_SEQ * IDIM];
__device__ __half g_wq16 [(size_t)(ODIM*2) * IDIM];
__device__ __half g_wkv16[(size_t)1024 * IDIM];     // rows 0-511 wk^T, 512-1023 wv^T
__device__ __half g_wo16 [(size_t)IDIM * ODIM];
__device__ __half g_y    [(size_t)L_SEQ * ODIM];
// attention operands (single fp16)
__device__ __half g_q16 [(size_t)L_SEQ * ODIM];     // pre-scaled
__device__ __half g_k16 [(size_t)L_SEQ * NKV];
__device__ __half g_v16 [(size_t)L_SEQ * NKV];
// split-KV partials (fixed-max: no m needed)
__device__ float g_opart[(size_t)512 * 64 * 256];
__device__ float g_lpart[(size_t)512 * 64];

// ---------------- cast kernel: fp32 -> fp16 ----------------
__global__ __launch_bounds__(256) void cast_h_kernel(
    const float* __restrict__ in, __half* __restrict__ out, size_t n4)
{
    size_t i = (size_t)blockIdx.x * blockDim.x + threadIdx.x;
    size_t stride = (size_t)gridDim.x * blockDim.x;
    for (; i < n4; i += stride) {
        float4 v = reinterpret_cast<const float4*>(in)[i];
        __half2 a = __halves2half2(__float2half_rn(v.x), __float2half_rn(v.y));
        __half2 b = __halves2half2(__float2half_rn(v.z), __float2half_rn(v.w));
        reinterpret_cast<__half2*>(out)[i*2]   = a;
        reinterpret_cast<__half2*>(out)[i*2+1] = b;
    }
}

// ---------------- combined transpose: all four weights in one launch ----------------
__device__ __forceinline__ void transpose_tile(
    const float* __restrict__ W, __half* __restrict__ T,
    int Kdim, int Ndim, int bxx, int byy)
{
    __shared__ float tile[32][33];
    int n0 = bxx * 32;
    int k0 = byy * 32;
    int tx = threadIdx.x & 31;
    int ty = threadIdx.x >> 5;
#pragma unroll
    for (int r = 0; r < 4; r++)
        tile[ty + 8*r][tx] = W[(size_t)(k0 + ty + 8*r) * Ndim + n0 + tx];
    __syncthreads();
#pragma unroll
    for (int r = 0; r < 4; r++) {
        float v = tile[tx][ty + 8*r];
        T[(size_t)(n0 + ty + 8*r) * Kdim + k0 + tx] = __float2half_rn(v);
    }
}

// grid: 8192 (wq) + 1024 (wk) + 1024 (wv) + 4096 (wo) = 14336 blocks
__global__ __launch_bounds__(256) void transpose_all_kernel(
    const float* __restrict__ wq, const float* __restrict__ wk,
    const float* __restrict__ wv, const float* __restrict__ wo,
    __half* __restrict__ wq16, __half* __restrict__ wkv16, __half* __restrict__ wo16)
{
    int bx = blockIdx.x;
    if (bx < 8192) {
        transpose_tile(wq, wq16, IDIM, ODIM*2, bx & 127, bx >> 7);
    } else if (bx < 9216) {
        int t = bx - 8192;
        transpose_tile(wk, wkv16, IDIM, NKV, t & 15, t >> 4);
    } else if (bx < 10240) {
        int t = bx - 9216;
        transpose_tile(wv, wkv16 + (size_t)512 * IDIM, IDIM, NKV, t & 15, t >> 4);
    } else {
        int t = bx - 10240;
        transpose_tile(wo, wo16, ODIM, IDIM, t & 63, t >> 6);
    }
}

// ---------------- 1-term fp16 GEMM body (device) ----------------
#define GBK 32
#define NCHUNK (IDIM / GBK)            // 64
#define RS 80                          // smem row stride bytes
#define MAT_BYTES (128 * RS)           // 10240
#define MAT2_STAGE (2 * MAT_BYTES)     // 20480
#define GEMM1_SMEM (2 * MAT2_STAGE)    // 40960

__device__ __forceinline__ void gemm_body(
    const __half* __restrict__ A, const __half* __restrict__ B,
    float* __restrict__ C, int N, int m0, int n0, char* smem)
{
    const uint32_t sb = smem_to_u32(smem);
    const int tid  = threadIdx.x;
    const int lane = tid & 31;
    const int wid  = tid >> 5;
    const int wm   = wid & 1;
    const int wn   = wid >> 1;

    auto issue_loads = [&](int chunk) {
        const int stage = chunk & 1;
        const uint32_t s0 = sb + stage * MAT2_STAGE;
#pragma unroll
        for (int j = 0; j < 4; j++) {
            int idx = tid + 256 * j;          // 0..1023
            int mat = idx >> 9;               // 0=A,1=B
            int wi  = idx & 511;
            int row = wi >> 2;
            int c   = wi & 3;
            const __half* gp = (mat == 0) ? A + (size_t)(m0 + row) * IDIM
                                          : B + (size_t)(n0 + row) * IDIM;
            cp_async16(s0 + mat * MAT_BYTES + row * RS + c * 16,
                       gp + chunk * GBK + c * 8);
        }
    };

    float acc[4][4][4];
#pragma unroll
    for (int mi = 0; mi < 4; mi++)
#pragma unroll
        for (int ni = 0; ni < 4; ni++)
#pragma unroll
            for (int r = 0; r < 4; r++) acc[mi][ni][r] = 0.0f;

    const uint32_t a_row = wm * 64 + (lane & 15);
    const uint32_t b_row = wn * 32 + (lane & 15);
    const uint32_t colb  = (lane >> 4) * 16;

    issue_loads(0); CP_COMMIT();

    for (int i = 0; i < NCHUNK; i++) {
        const int stage = i & 1;
        if (i + 1 < NCHUNK) { issue_loads(i + 1); CP_COMMIT(); CP_WAIT1(); }
        else                { CP_WAIT0(); }
        __syncthreads();

        const uint32_t sA = sb + stage * MAT2_STAGE;
        const uint32_t sB = sA + MAT_BYTES;

#pragma unroll
        for (int ks = 0; ks < 2; ks++) {
            const uint32_t kb = ks * 32 + colb;
            uint32_t a[4][4], b[2][4];
#pragma unroll
            for (int mi = 0; mi < 4; mi++)
                ldsm_x4(a[mi], sA + (a_row + mi * 16) * RS + kb);
#pragma unroll
            for (int nt = 0; nt < 2; nt++)
                ldsm_x4(b[nt], sB + (b_row + nt * 16) * RS + kb);
#pragma unroll
            for (int mi = 0; mi < 4; mi++) {
#pragma unroll
                for (int ni = 0; ni < 4; ni++) {
                    const int nt = ni >> 1, sub = ni & 1;
                    mma16816h(acc[mi][ni], a[mi], b[nt][sub], b[nt][2 + sub]);
                }
            }
        }
        __syncthreads();
    }

    const int er = lane >> 2;
    const int ec = (lane & 3) * 2;
#pragma unroll
    for (int mi = 0; mi < 4; mi++) {
#pragma unroll
        for (int ni = 0; ni < 4; ni++) {
            int row = m0 + wm * 64 + mi * 16 + er;
            int col = n0 + wn * 32 + ni * 8 + ec;
            *reinterpret_cast<float2*>(&C[(size_t)row * N + col]) =
                make_float2(acc[mi][ni][0], acc[mi][ni][1]);
            *reinterpret_cast<float2*>(&C[(size_t)(row + 8) * N + col]) =
                make_float2(acc[mi][ni][2], acc[mi][ni][3]);
        }
    }
}

// standalone GEMM (wo projection)
__global__ __launch_bounds__(256) void mma_gemmh(
    const __half* __restrict__ A, const __half* __restrict__ B,
    float* __restrict__ C, int N)
{
    extern __shared__ char smem[];
    gemm_body(A, B, C, N, blockIdx.y * 128, blockIdx.x * 128, smem);
}

// combined Q + KV projection: blocks 0..1023 -> Q proj, 1024..1279 -> KV proj
__global__ __launch_bounds__(256) void mma_proj_kernel(
    const __half* __restrict__ x16,
    const __half* __restrict__ wq16, const __half* __restrict__ wkv16,
    float* __restrict__ qraw, float* __restrict__ kvraw)
{
    extern __shared__ char smem[];
    int bx = blockIdx.x;
    if (bx < 1024) {
        gemm_body(x16, wq16, qraw, ODIM*2, (bx >> 5) * 128, (bx & 31) * 128, smem);
    } else {
        int t = bx - 1024;
        gemm_body(x16, wkv16, kvraw, 1024, (t >> 3) * 128, (t & 7) * 128, smem);
    }
}

// ---------------- warp-per-row norm bodies ----------------
__device__ __forceinline__ void qnorm_body(
    const float* __restrict__ cosb, const float* __restrict__ sinb,
    const float* __restrict__ gamma, int ridx, int lane)
{
    const int l = ridx >> 3, h = ridx & 7;
    const float* row = g_qraw + (size_t)l * (ODIM * 2) + h * 512;

    float4 a = *reinterpret_cast<const float4*>(row + lane * 8);
    float4 b = *reinterpret_cast<const float4*>(row + lane * 8 + 4);
    float y[8] = {a.x, a.y, a.z, a.w, b.x, b.y, b.z, b.w};

    float s = 0.0f;
#pragma unroll
    for (int j = 0; j < 8; j++) s += y[j] * y[j];
#pragma unroll
    for (int o = 16; o > 0; o >>= 1) s += __shfl_xor_sync(0xffffffffu, s, o);
    float rstd = rsqrtf(s * (1.0f / 256.0f) + 1e-6f);

    float4 ga = *reinterpret_cast<const float4*>(gamma + lane * 8);
    float4 gb = *reinterpret_cast<const float4*>(gamma + lane * 8 + 4);
    float gm[8] = {ga.x, ga.y, ga.z, ga.w, gb.x, gb.y, gb.z, gb.w};
#pragma unroll
    for (int j = 0; j < 8; j++) y[j] *= rstd * gm[j];

    float oth[8];
#pragma unroll
    for (int j = 0; j < 8; j++) oth[j] = __shfl_xor_sync(0xffffffffu, y[j], 4);
    if (lane < 8) {
        const float* cb  = cosb + (size_t)l * ROPED + lane * 8;
        const float* sbp = sinb + (size_t)l * ROPED + lane * 8;
#pragma unroll
        for (int j = 0; j < 8; j++) {
            float rot = (lane < 4) ? -oth[j] : oth[j];
            y[j] = y[j] * cb[j] + rot * sbp[j];
        }
    }

    float4 g0 = *reinterpret_cast<const float4*>(row + 256 + lane * 8);
    float4 g1 = *reinterpret_cast<const float4*>(row + 256 + lane * 8 + 4);
    float gv[8] = {g0.x, g0.y, g0.z, g0.w, g1.x, g1.y, g1.z, g1.w};

    size_t o = (size_t)l * ODIM + h * HDIM + lane * 8;
    uint32_t qw[4], gw[4];
#pragma unroll
    for (int j = 0; j < 4; j++) {
        qw[j] = pack_h2(__float2half_rn(y[j*2] * QSCALE), __float2half_rn(y[j*2+1] * QSCALE));
        gw[j] = pack_h2(__float2half_rn(gv[j*2]), __float2half_rn(gv[j*2+1]));
    }
    *reinterpret_cast<uint4*>(&g_q16[o])    = make_uint4(qw[0], qw[1], qw[2], qw[3]);
    *reinterpret_cast<uint4*>(&g_gate16[o]) = make_uint4(gw[0], gw[1], gw[2], gw[3]);
}

__device__ __forceinline__ void knorm_body(
    const float* __restrict__ cosb, const float* __restrict__ sinb,
    const float* __restrict__ gamma, int ridx, int lane)
{
    const int l = ridx >> 1, g = ridx & 1;
    const float* krow = g_kvraw + (size_t)l * 1024 + g * HDIM;
    const float* vrow = g_kvraw + (size_t)l * 1024 + 512 + g * HDIM;

    float4 a = *reinterpret_cast<const float4*>(krow + lane * 8);
    float4 b = *reinterpret_cast<const float4*>(krow + lane * 8 + 4);
    float y[8] = {a.x, a.y, a.z, a.w, b.x, b.y, b.z, b.w};

    float s = 0.0f;
#pragma unroll
    for (int j = 0; j < 8; j++) s += y[j] * y[j];
#pragma unroll
    for (int o = 16; o > 0; o >>= 1) s += __shfl_xor_sync(0xffffffffu, s, o);
    float rstd = rsqrtf(s * (1.0f / 256.0f) + 1e-6f);

    float4 ga = *reinterpret_cast<const float4*>(gamma + lane * 8);
    float4 gb = *reinterpret_cast<const float4*>(gamma + lane * 8 + 4);
    float gm[8] = {ga.x, ga.y, ga.z, ga.w, gb.x, gb.y, gb.z, gb.w};
#pragma unroll
    for (int j = 0; j < 8; j++) y[j] *= rstd * gm[j];

    float oth[8];
#pragma unroll
    for (int j = 0; j < 8; j++) oth[j] = __shfl_xor_sync(0xffffffffu, y[j], 4);
    if (lane < 8) {
        const float* cb  = cosb + (size_t)l * ROPED + lane * 8;
        const float* sbp = sinb + (size_t)l * ROPED + lane * 8;
#pragma unroll
        for (int j = 0; j < 8; j++) {
            float rot = (lane < 4) ? -oth[j] : oth[j];
            y[j] = y[j] * cb[j] + rot * sbp[j];
        }
    }

    float4 v0 = *reinterpret_cast<const float4*>(vrow + lane * 8);
    float4 v1 = *reinterpret_cast<const float4*>(vrow + lane * 8 + 4);
    float vv[8] = {v0.x, v0.y, v0.z, v0.w, v1.x, v1.y, v1.z, v1.w};

    size_t o = (size_t)l * NKV + g * HDIM + lane * 8;
    uint32_t kw[4], vw[4];
#pragma unroll
    for (int j = 0; j < 4; j++) {
        kw[j] = pack_h2(__float2half_rn(y[j*2]), __float2half_rn(y[j*2+1]));
        vw[j] = pack_h2(__float2half_rn(vv[j*2]), __float2half_rn(vv[j*2+1]));
    }
    *reinterpret_cast<uint4*>(&g_k16[o]) = make_uint4(kw[0], kw[1], kw[2], kw[3]);
    *reinterpret_cast<uint4*>(&g_v16[o]) = make_uint4(vw[0], vw[1], vw[2], vw[3]);
}

// combined norms: blocks 0..4095 -> Q rows, 4096..5119 -> K/V rows
__global__ __launch_bounds__(256) void norm_all_kernel(
    const float* __restrict__ cosb, const float* __restrict__ sinb,
    const float* __restrict__ qg, const float* __restrict__ kg)
{
    const int lane = threadIdx.x & 31;
    const int w = threadIdx.x >> 5;
    int bx = blockIdx.x;
    if (bx < 4096) qnorm_body(cosb, sinb, qg, bx * 8 + w, lane);
    else           knorm_body(cosb, sinb, kg, (bx - 4096) * 8 + w, lane);
}

// ---------------- MMA flash attention, fixed-max softmax, split-KV ----------------
#define AQ   0
#define AK   32768
#define AV   65536
#define AP   98304
#define APS  (AP + 8192)
#define ATT_SMEM (APS + 512)        // 107008

__device__ __forceinline__ uint32_t sw512(int row, int g) {
    return (uint32_t)(row * 512 + ((g ^ (row & 7)) << 4));
}
__device__ __forceinline__ uint32_t sw128(int row, int g) {
    return (uint32_t)(row * 128 + ((g ^ (row & 7)) << 4));
}

// grid (96, 8): bx 0..63 = split pieces; bx 64..95 = full blocks (qt 31..0)
__global__ __launch_bounds__(256, 2) void attn_mma_kernel()
{
    extern __shared__ char sm[];
    const uint32_t sb = smem_to_u32(sm);
    const int tid  = threadIdx.x;
    const int lane = tid & 31;
    const int wid  = tid >> 5;
    const int bx   = blockIdx.x;
    const int h    = blockIdx.y;
    const int g    = h >> 2;

    int qt, jt0, jt1, half;
    bool is_split;
    if (bx < 64) {
        is_split = true;
        half = bx & 1;
        qt = 63 - (bx >> 1);
        int nt = qt + 1;
        int sp = nt >> 1;
        jt0 = half ? sp : 0;
        jt1 = half ? nt : sp;
    } else {
        is_split = false;
        half = 0;
        qt = 95 - bx;
        jt0 = 0;
        jt1 = qt + 1;
    }
    const int i0  = qt * 64;
    const int jlo = jt0 * 64;
    const int jhi = (jt1 - 1) * 64;

    float* psum = reinterpret_cast<float*>(sm + APS);

    auto load_k = [&](int j0) {
        const size_t rbase = ((size_t)j0 * NGROUPS + g) * HDIM;
        const size_t rstr  = (size_t)NGROUPS * HDIM;
#pragma unroll
        for (int i = 0; i < 8; i++) {
            int idx = tid + 256 * i;
            int row = idx >> 5, gr = idx & 31;
            cp_async16(sb + AK + sw512(row, gr),
                       (const char*)g_k16 + (rbase + (size_t)row * rstr) * 2 + gr * 16);
        }
    };
    auto load_v = [&](int j0) {
        const size_t rbase = ((size_t)j0 * NGROUPS + g) * HDIM;
        const size_t rstr  = (size_t)NGROUPS * HDIM;
#pragma unroll
        for (int i = 0; i < 8; i++) {
            int idx = tid + 256 * i;
            int row = idx >> 5, gr = idx & 31;
            cp_async16(sb + AV + sw512(row, gr),
                       (const char*)g_v16 + (rbase + (size_t)row * rstr) * 2 + gr * 16);
        }
    };

    // ---- prolog: Q, K(jlo), V(jlo) ----
    {
        const char* q16 = (const char*)(g_q16 + ((size_t)i0 * NHEADS + h) * HDIM);
        const size_t rstr = (size_t)NHEADS * HDIM * 2;
#pragma unroll
        for (int i = 0; i < 8; i++) {
            int idx = tid + 256 * i;
            int row = idx >> 5, gr = idx & 31;
            cp_async16(sb + AQ + sw512(row, gr), q16 + (size_t)row * rstr + gr * 16);
        }
    }
    CP_COMMIT();
    load_k(jlo); CP_COMMIT();
    load_v(jlo); CP_COMMIT();

    const int wm = wid & 3;
    const int wn = wid >> 2;
    const int er = lane >> 2;
    const int ec = (lane & 3) * 2;
    const int kgl = lane >> 4;
    const int r0 = wm * 16 + er;
    const int r1 = r0 + 8;

    float oacc[16][4];
#pragma unroll
    for (int t = 0; t < 16; t++)
#pragma unroll
        for (int r = 0; r < 4; r++) oacc[t][r] = 0.0f;
    float lac0 = 0.0f, lac1 = 0.0f;

    for (int j0 = jlo; j0 <= jhi; j0 += 64) {
        CP_WAIT1();
        __syncthreads();

        // ---- S = Q K^T ----
        float sacc[4][4];
#pragma unroll
        for (int t = 0; t < 4; t++)
#pragma unroll
            for (int r = 0; r < 4; r++) sacc[t][r] = 0.0f;

        const int arow  = wm * 16 + (lane & 15);
        const int brow0 = wn * 32 + (lane & 15);
#pragma unroll 4
        for (int ks = 0; ks < 16; ks++) {
            int kg = ks * 2 + kgl;
            uint32_t a[4], b[2][4];
            ldsm_x4(a, sb + AQ + sw512(arow, kg));
            ldsm_x4(b[0], sb + AK + sw512(brow0, kg));
            ldsm_x4(b[1], sb + AK + sw512(brow0 + 16, kg));
#pragma unroll
            for (int nt = 0; nt < 2; nt++)
#pragma unroll
                for (int sub = 0; sub < 2; sub++)
                    mma16816h(sacc[nt * 2 + sub], a, b[nt][sub], b[nt][2 + sub]);
        }

        // ---- fixed-max softmax: p = exp(S - 8) ----
        {
            const int lim0 = i0 + r0 - j0;
            const int lim1 = lim0 + 8;
            uint32_t pw0[4], pw1[4];
#pragma unroll
            for (int t = 0; t < 4; t++) {
                int col = wn * 32 + (t >> 1) * 16 + (t & 1) * 8 + ec;
                if (col > lim0)     sacc[t][0] = -INFINITY;
                if (col + 1 > lim0) sacc[t][1] = -INFINITY;
                if (col > lim1)     sacc[t][2] = -INFINITY;
                if (col + 1 > lim1) sacc[t][3] = -INFINITY;
                float p00 = __expf(sacc[t][0] - SMAX);
                float p01 = __expf(sacc[t][1] - SMAX);
                float p10 = __expf(sacc[t][2] - SMAX);
                float p11 = __expf(sacc[t][3] - SMAX);
                lac0 += p00 + p01; lac1 += p10 + p11;
                pw0[t] = pack_h2(__float2half_rn(p00), __float2half_rn(p01));
                pw1[t] = pack_h2(__float2half_rn(p10), __float2half_rn(p11));
            }
#pragma unroll
            for (int t = 0; t < 4; t++) {
                int gidx = wn * 4 + (t >> 1) * 2 + (t & 1);
                *reinterpret_cast<uint32_t*>(sm + AP + sw128(r0, gidx) + (lane & 3) * 4) = pw0[t];
                *reinterpret_cast<uint32_t*>(sm + AP + sw128(r1, gidx) + (lane & 3) * 4) = pw1[t];
            }
        }
        __syncthreads();          // P visible; K buffer dead

        if (j0 + 64 <= jhi) load_k(j0 + 64);
        CP_COMMIT();
        CP_WAIT1();               // V(j0) ready
        __syncthreads();

        // ---- O += P V ----
        const int prow = wm * 16 + (lane & 15);
        const int vk   = lane & 15;
        const int vng  = lane >> 4;
#pragma unroll
        for (int ks = 0; ks < 4; ks++) {
            uint32_t a[4];
            ldsm_x4(a, sb + AP + sw128(prow, ks * 2 + kgl));
            int krow = ks * 16 + vk;
#pragma unroll
            for (int ng = 0; ng < 8; ng++) {
                uint32_t vv[4];
                int gv = wn * 16 + ng * 2 + vng;
                ldsm_x4_trans(vv, sb + AV + sw512(krow, gv));
#pragma unroll
                for (int sub = 0; sub < 2; sub++)
                    mma16816h(oacc[ng * 2 + sub], a, vv[2 * sub], vv[2 * sub + 1]);
            }
        }
        __syncthreads();          // V buffer dead

        if (j0 + 64 <= jhi) load_v(j0 + 64);
        CP_COMMIT();
    }

    // ---- final l reduction ----
    lac0 += __shfl_xor_sync(0xffffffffu, lac0, 1);
    lac0 += __shfl_xor_sync(0xffffffffu, lac0, 2);
    lac1 += __shfl_xor_sync(0xffffffffu, lac1, 1);
    lac1 += __shfl_xor_sync(0xffffffffu, lac1, 2);
    if ((lane & 3) == 0) { psum[wn * 64 + r0] = lac0; psum[wn * 64 + r1] = lac1; }
    __syncthreads();

    if (is_split) {
        const int p = ((qt - 32) * 8 + h) * 2 + half;
        float* Op = g_opart + (size_t)p * 64 * 256;
        if (tid < 64) g_lpart[p * 64 + tid] = psum[tid] + psum[64 + tid];
#pragma unroll
        for (int t = 0; t < 16; t++) {
            int col = wn * 128 + (t >> 1) * 16 + (t & 1) * 8 + ec;
            *reinterpret_cast<float2*>(&Op[r0 * 256 + col]) =
                make_float2(oacc[t][0], oacc[t][1]);
            *reinterpret_cast<float2*>(&Op[(r0 + 8) * 256 + col]) =
                make_float2(oacc[t][2], oacc[t][3]);
        }
    } else {
        const float li0 = 1.0f / (psum[r0] + psum[64 + r0]);
        const float li1 = 1.0f / (psum[r1] + psum[64 + r1]);
        const size_t base0 = (size_t)(i0 + r0) * ODIM + h * HDIM;
        const size_t base1 = (size_t)(i0 + r1) * ODIM + h * HDIM;
#pragma unroll
        for (int t = 0; t < 16; t++) {
            int col = wn * 128 + (t >> 1) * 16 + (t & 1) * 8 + ec;
            __half2 gh0 = *reinterpret_cast<const __half2*>(&g_gate16[base0 + col]);
            __half2 gh1 = *reinterpret_cast<const __half2*>(&g_gate16[base1 + col]);
            float2 gt0 = __half22float2(gh0);
            float2 gt1 = __half22float2(gh1);
            float v00 = oacc[t][0] * li0 * (1.0f / (1.0f + __expf(-gt0.x)));
            float v01 = oacc[t][1] * li0 * (1.0f / (1.0f + __expf(-gt0.y)));
            float v10 = oacc[t][2] * li1 * (1.0f / (1.0f + __expf(-gt1.x)));
            float v11 = oacc[t][3] * li1 * (1.0f / (1.0f + __expf(-gt1.y)));
            *reinterpret_cast<__half2*>(&g_y[base0 + col]) =
                __halves2half2(__float2half_rn(v00), __float2half_rn(v01));
            *reinterpret_cast<__half2*>(&g_y[base1 + col]) =
                __halves2half2(__float2half_rn(v10), __float2half_rn(v11));
        }
    }
}

// ---------------- split-KV merge (fixed-max) ----------------
__global__ __launch_bounds__(256) void attn_merge_kernel()
{
    const int lr = blockIdx.x;           // 0..2047 (rows 2048..4095)
    const int h  = blockIdx.y;
    const int qt  = 32 + (lr >> 6);
    const int row = lr & 63;
    const int p0 = ((qt - 32) * 8 + h) * 2;

    const float l1 = g_lpart[p0 * 64 + row];
    const float l2 = g_lpart[(p0 + 1) * 64 + row];
    const float inv = 1.0f / (l1 + l2);

    const float* O1 = g_opart + ((size_t)p0 * 64 + row) * 256;
    const float* O2 = g_opart + ((size_t)(p0 + 1) * 64 + row) * 256;
    const int col = threadIdx.x;
    const size_t base = (size_t)(2048 + lr) * ODIM + h * HDIM;

    float o = (O1[col] + O2[col]) * inv;
    float gt = __half2float(g_gate16[base + col]);
    g_y[base + col] = __float2half_rn(o * (1.0f / (1.0f + __expf(-gt))));
}

// ---------------- launch ----------------
extern "C" void kernel_launch(void* const* d_in, const int* in_sizes, int n_in,
                              void* d_out, int out_size)
{
    const float* x    = (const float*)d_in[0];
    const float* cosb = (const float*)d_in[1];
    const float* sinb = (const float*)d_in[2];
    const float* wq   = (const float*)d_in[4];
    const float* wk   = (const float*)d_in[5];
    const float* wv   = (const float*)d_in[6];
    const float* wo   = (const float*)d_in[7];
    const float* qg   = (const float*)d_in[8];
    const float* kg   = (const float*)d_in[9];
    float* out        = (float*)d_out;

    float *p_qraw, *p_kvraw;
    cudaGetSymbolAddress((void**)&p_qraw,  g_qraw);
    cudaGetSymbolAddress((void**)&p_kvraw, g_kvraw);

    __half *p_x16, *p_wq16, *p_wkv16, *p_wo16, *p_y;
    cudaGetSymbolAddress((void**)&p_x16,   g_x16);
    cudaGetSymbolAddress((void**)&p_wq16,  g_wq16);
    cudaGetSymbolAddress((void**)&p_wkv16, g_wkv16);
    cudaGetSymbolAddress((void**)&p_wo16,  g_wo16);
    cudaGetSymbolAddress((void**)&p_y,     g_y);

    cudaFuncSetAttribute(mma_gemmh, cudaFuncAttributeMaxDynamicSharedMemorySize, GEMM1_SMEM);
    cudaFuncSetAttribute(mma_proj_kernel, cudaFuncAttributeMaxDynamicSharedMemorySize, GEMM1_SMEM);
    cudaFuncSetAttribute(attn_mma_kernel, cudaFuncAttributeMaxDynamicSharedMemorySize, ATT_SMEM);

    // 0) operand prep: cast + all weight transposes (2 launches)
    cast_h_kernel<<<2048, 256>>>(x, p_x16, (size_t)L_SEQ * IDIM / 4);
    transpose_all_kernel<<<14336, 256>>>(wq, wk, wv, wo, p_wq16, p_wkv16, p_wo16);

    // 1) combined Q + KV projection (one launch, packed waves)
    mma_proj_kernel<<<1280, 256, GEMM1_SMEM>>>(p_x16, p_wq16, p_wkv16, p_qraw, p_kvraw);

    // 2) combined norms + RoPE (one launch)
    norm_all_kernel<<<5120, 256>>>(cosb, sinb, qg, kg);

    // 3) split-KV MMA flash attention (fixed-max softmax) + merge
    attn_mma_kernel<<<dim3(96, NHEADS), 256, ATT_SMEM>>>();
    attn_merge_kernel<<<dim3(2048, NHEADS), 256>>>();

    // 4) output projection
    mma_gemmh<<<dim3(IDIM/128, L_SEQ/128), 256, GEMM1_SMEM>>>(p_y, p_wo16, out, IDIM);
}